// round 13
// baseline (speedup 1.0000x reference)
#include <cuda_runtime.h>
#include <cuda_fp16.h>
#include <math.h>
#include <stdint.h>

#define VCAB 50257
#define EDIM 256
#define HDIM 512
#define BATCH 64
#define SLEN 128
#define TLEN 64
#define TD 63            // decoder steps (T-1)
#define GDIM 2048        // 4*H

// fc GEMM dims (fp16 mma.sync path)
#define KD 1024
#define MPAD 4096
#define NPAD 50432       // 197 * 256
#define NCHK 16          // KD / 64
#define STGB 49152       // fc stage bytes: A 16KB + B 32KB

// ---------------- scratch (static device allocations; no cudaMalloc) ----------------
__device__ __align__(16) float g_bIenc[GDIM];
__device__ __align__(16) float g_bIdec[GDIM];
__device__ __align__(16) float g_xprojE[(size_t)SLEN * BATCH * GDIM];  // INTERLEAVED [m][j*4+g]
__device__ __align__(16) float g_decxp[(size_t)MPAD * GDIM];           // INTERLEAVED
__device__ __align__(16) float g_c[BATCH * HDIM];
__device__ __align__(16) float g_hwh[BATCH * HDIM];
// fp16 embeddings / states
__device__ __align__(16) __half g_encX16[(size_t)SLEN * BATCH * EDIM];
__device__ __align__(16) __half g_decX16[(size_t)MPAD * EDIM];
__device__ __align__(16) __half g_encout16[(size_t)BATCH * SLEN * HDIM];
__device__ __align__(16) __half g_encWe16[(size_t)BATCH * SLEN * HDIM];
__device__ __align__(16) __half g_eh16[2][BATCH * HDIM];
__device__ __align__(16) __half g_xh16[2][BATCH * 1024];
// fp16 gate-interleaved weights
__device__ __align__(16) __half g_We16[(size_t)GDIM * HDIM];
__device__ __align__(16) __half g_Wd16[(size_t)GDIM * 1024];
__device__ __align__(16) __half g_WihE16[(size_t)GDIM * EDIM];
__device__ __align__(16) __half g_WihD16[(size_t)GDIM * EDIM];
// attention weights [n][k]
__device__ __align__(16) __half g_Wh16[(size_t)HDIM * HDIM];
__device__ __align__(16) __half g_Wat16[(size_t)HDIM * HDIM];
// fp16 operands for the tensor-core fc GEMM (pad rows stay zero: never written)
__device__ __align__(16) __half g_Ahf[(size_t)MPAD * KD];
__device__ __align__(16) __half g_Bhf[(size_t)NPAD * KD];

__device__ __forceinline__ float sigf(float x) { return 1.0f / (1.0f + expf(-x)); }

// ---------------- PTX helpers (compute_103-safe) ----------------
__device__ __forceinline__ uint32_t smem_u32(const void* p) {
    uint32_t a;
    asm("{ .reg .u64 t; cvta.to.shared.u64 t, %1; cvt.u32.u64 %0, t; }" : "=r"(a) : "l"(p));
    return a;
}
__device__ __forceinline__ void cpa16(uint32_t dst, const void* src) {
    asm volatile("cp.async.cg.shared.global [%0], [%1], 16;" :: "r"(dst), "l"(src) : "memory");
}
__device__ __forceinline__ void cpa_commit() { asm volatile("cp.async.commit_group;" ::: "memory"); }
template <int N> __device__ __forceinline__ void cpa_wait() {
    asm volatile("cp.async.wait_group %0;" :: "n"(N) : "memory");
}
#define LDMX4(r, addr) \
    asm volatile("ldmatrix.sync.aligned.m8n8.x4.shared.b16 {%0,%1,%2,%3}, [%4];" \
        : "=r"((r)[0]), "=r"((r)[1]), "=r"((r)[2]), "=r"((r)[3]) : "r"(addr))
__device__ __forceinline__ void mma16816(float* c, const uint32_t* a, uint32_t b0, uint32_t b1) {
    asm volatile("mma.sync.aligned.m16n8k16.row.col.f32.f16.f16.f32 "
        "{%0,%1,%2,%3}, {%4,%5,%6,%7}, {%8,%9}, {%0,%1,%2,%3};"
        : "+f"(c[0]), "+f"(c[1]), "+f"(c[2]), "+f"(c[3])
        : "r"(a[0]), "r"(a[1]), "r"(a[2]), "r"(a[3]), "r"(b0), "r"(b1));
}

// ---------------- setup kernels ----------------
__global__ void k_biasI(const float* __restrict__ ebih, const float* __restrict__ ebhh,
                        const float* __restrict__ dbih, const float* __restrict__ dbhh) {
    int n = blockIdx.x * blockDim.x + threadIdx.x;
    if (n < GDIM) {
        int j = n >> 2, g = n & 3;
        int r = g * 512 + j;
        g_bIenc[n] = ebih[r] + ebhh[r];
        g_bIdec[n] = dbih[r] + dbhh[r];
    }
}

__global__ void k_w16_enc(const float* __restrict__ Whh) {
    size_t idx = (size_t)blockIdx.x * blockDim.x + threadIdx.x;
    if (idx >= (size_t)GDIM * HDIM) return;
    int n = (int)(idx >> 9);
    int k = (int)(idx & 511);
    int j = n >> 2, g = n & 3;
    g_We16[idx] = __float2half(Whh[(size_t)(g * 512 + j) * 512 + k]);
}

__global__ void k_w16_dec(const float* __restrict__ dWih, const float* __restrict__ dWhh) {
    size_t idx = (size_t)blockIdx.x * blockDim.x + threadIdx.x;
    if (idx >= (size_t)GDIM * 1024) return;
    int n = (int)(idx >> 10);
    int k = (int)(idx & 1023);
    int j = n >> 2, g = n & 3;
    int row = g * 512 + j;
    float v = (k < 512) ? dWhh[(size_t)row * 512 + k]
                        : dWih[(size_t)row * (EDIM + HDIM) + EDIM + (k - 512)];
    g_Wd16[idx] = __float2half(v);
}

__global__ void k_w16_attn(const float* __restrict__ attnW) {
    size_t idx = (size_t)blockIdx.x * blockDim.x + threadIdx.x;
    if (idx >= (size_t)HDIM * HDIM) return;
    int n = (int)(idx >> 9);
    int k = (int)(idx & 511);
    g_Wh16[idx] = __float2half(attnW[(size_t)n * 1024 + k]);
    g_Wat16[idx] = __float2half(attnW[(size_t)n * 1024 + 512 + k]);
}

__global__ void k_w16_wih(const float* __restrict__ eWih, const float* __restrict__ dWih) {
    size_t idx = (size_t)blockIdx.x * blockDim.x + threadIdx.x;
    if (idx >= (size_t)GDIM * EDIM) return;
    int n = (int)(idx >> 8);
    int k = (int)(idx & 255);
    int j = n >> 2, g = n & 3;
    int row = g * 512 + j;
    g_WihE16[idx] = __float2half(eWih[(size_t)row * EDIM + k]);
    g_WihD16[idx] = __float2half(dWih[(size_t)row * (EDIM + HDIM) + k]);
}

__global__ void k_gather_enc(const float* __restrict__ emb, const int* __restrict__ src) {
    int m = blockIdx.x;
    int e = threadIdx.x;
    int s = m >> 6, b = m & 63;
    int tok = src[b * SLEN + s];
    g_encX16[(size_t)m * EDIM + e] = __float2half(emb[(size_t)tok * EDIM + e]);
}

__global__ void k_gather_dec(const float* __restrict__ emb, const int* __restrict__ trg) {
    int m = blockIdx.x;
    int e = threadIdx.x;
    int t = m >> 6, b = m & 63;
    int tok = trg[b * TLEN + t];
    g_decX16[(size_t)m * EDIM + e] = __float2half(emb[(size_t)tok * EDIM + e]);
}

__global__ void k_zero_out(float* __restrict__ out) {
    size_t idx = (size_t)blockIdx.x * blockDim.x + threadIdx.x;
    if (idx >= (size_t)BATCH * VCAB) return;
    size_t b = idx / VCAB, v = idx % VCAB;
    out[b * (size_t)TLEN * VCAB + v] = 0.0f;
}

__global__ void k_zero_state() {
    int i = blockIdx.x * blockDim.x + threadIdx.x;
    if (i < BATCH * HDIM) {
        g_eh16[0][i] = __float2half(0.0f);
        g_c[i] = 0.0f;
    }
}

__global__ void k_init_dec() {
    int i = blockIdx.x * blockDim.x + threadIdx.x;
    int b = i >> 9, j = i & 511;
    g_xh16[0][b * 1024 + j] = g_eh16[0][b * 512 + j];
}

__global__ void k_convB_h(const float* __restrict__ W) {
    size_t i4 = (size_t)blockIdx.x * blockDim.x + threadIdx.x;
    if (i4 * 4 >= (size_t)VCAB * KD) return;
    float4 v = *reinterpret_cast<const float4*>(W + i4 * 4);
    __half2* dst = reinterpret_cast<__half2*>(g_Bhf + i4 * 4);
    dst[0] = __floats2half2_rn(v.x, v.y);
    dst[1] = __floats2half2_rn(v.z, v.w);
}

// ============ shared fp16 GEMM tile machinery ============
template <int NCH>
__device__ __forceinline__ void load_AB16(uint32_t Ab, uint32_t Bb,
                                          const __half* __restrict__ Aglob, int apitchB,
                                          const __half* __restrict__ Bglob, int bpitchB,
                                          int n0, int tid) {
    for (int i = tid; i < 64 * 8 * NCH; i += 256) {
        int kc = i >> 9, rem = i & 511;
        int r = rem >> 3, s = rem & 7;
        uint32_t dst = Ab + kc * 8192 + (r << 7) + (((s ^ (r & 7)) << 4));
        const char* src = (const char*)Aglob + (size_t)r * apitchB + kc * 128 + (s << 4);
        cpa16(dst, src);
    }
    for (int i = tid; i < 32 * 8 * NCH; i += 256) {
        int kc = i >> 8, rem = i & 255;
        int r = rem >> 3, s = rem & 7;
        uint32_t dst = Bb + kc * 4096 + (r << 7) + (((s ^ (r & 7)) << 4));
        const char* src = (const char*)Bglob + (size_t)(n0 + r) * bpitchB + kc * 128 + (s << 4);
        cpa16(dst, src);
    }
    cpa_commit();
    cpa_wait<0>();
    __syncthreads();
}

template <int NCH>
__device__ __forceinline__ void mma_64x32(uint32_t Ab, uint32_t Bb, int lane, int wm, int wn,
                                          float acc[2][4]) {
    const int g = lane >> 3, lr = lane & 7;
    for (int kc = 0; kc < NCH; kc++) {
#pragma unroll
        for (int ks = 0; ks < 4; ks++) {
            uint32_t afr[4], bfr[4];
            {
                int row = wm * 16 + (g & 1) * 8 + lr;
                int kseg = ks * 2 + (g >> 1);
                uint32_t addr = Ab + kc * 8192 + (row << 7) + (((kseg ^ (row & 7)) << 4));
                LDMX4(afr, addr);
            }
            {
                int row = wn * 16 + (g >> 1) * 8 + lr;
                int kseg = ks * 2 + (g & 1);
                uint32_t addr = Bb + kc * 4096 + (row << 7) + (((kseg ^ (row & 7)) << 4));
                LDMX4(bfr, addr);
            }
            mma16816(acc[0], afr, bfr[0], bfr[1]);
            mma16816(acc[1], afr, bfr[2], bfr[3]);
        }
    }
}

// ---------------- fp16 projection GEMM (generalized): C = A @ B^T + bias ----------------
// sel 0: encoder xproj (K=256) | sel 1: decoder xproj (K=256) | sel 2: encWe (K=512, fp16 out)
__global__ void __launch_bounds__(256, 1) hgemm_proj(int sel, const float* __restrict__ bias_ext) {
    const __half* A;
    const __half* B;
    const float* biasI;
    float* C = nullptr;
    int Mlim, ldc, kch, kpitch;
    if (sel == 0) {
        A = g_encX16; B = g_WihE16; biasI = g_bIenc; C = g_xprojE;
        Mlim = SLEN * BATCH; ldc = GDIM; kch = 4; kpitch = EDIM * 2;
    } else if (sel == 1) {
        A = g_decX16; B = g_WihD16; biasI = g_bIdec; C = g_decxp;
        Mlim = TD * BATCH; ldc = GDIM; kch = 4; kpitch = EDIM * 2;
    } else {
        A = g_encout16; B = g_Wat16; biasI = bias_ext;
        Mlim = SLEN * BATCH; ldc = HDIM; kch = 8; kpitch = HDIM * 2;
    }

    extern __shared__ char smc[];
    const uint32_t sbase = smem_u32(smc);
    const int tid = threadIdx.x;
    const int wid = tid >> 5, lane = tid & 31;
    const int m0 = blockIdx.x * 128;
    const int n0 = blockIdx.y * 128;
    const int wm = wid >> 2, wn = wid & 3;

    const char* Ag = (const char*)A + (size_t)m0 * kpitch;
    const char* Bg = (const char*)B + (size_t)n0 * kpitch;

    float acc[4][4][4];
#pragma unroll
    for (int i = 0; i < 4; i++)
#pragma unroll
        for (int j = 0; j < 4; j++)
#pragma unroll
            for (int r = 0; r < 4; r++) acc[i][j][r] = 0.0f;

    auto load_chunk = [&](int kc, int slot) {
        uint32_t st = sbase + (uint32_t)slot * 32768;
#pragma unroll
        for (int i = 0; i < 8; i++) {
            int idx = tid + (i << 8);
            int isB = idx >> 10;
            int r = (idx & 1023) >> 3;
            int seg = idx & 7;
            uint32_t dst = st + (isB ? 16384u : 0u) + (uint32_t)(r << 7)
                         + (uint32_t)(((seg ^ (r & 7)) << 4));
            const char* src = (isB ? Bg : Ag) + (size_t)r * kpitch + (size_t)kc * 128 + (seg << 4);
            cpa16(dst, src);
        }
        cpa_commit();
    };

    const int g = lane >> 3, lr = lane & 7;
    auto compute = [&](int slot) {
        uint32_t Abase = sbase + (uint32_t)slot * 32768;
        uint32_t Bbase = Abase + 16384u;
#pragma unroll
        for (int ks = 0; ks < 4; ks++) {
            uint32_t afr[4][4];
#pragma unroll
            for (int mt = 0; mt < 4; mt++) {
                int row = wm * 64 + mt * 16 + (g & 1) * 8 + lr;
                int kseg = ks * 2 + (g >> 1);
                uint32_t addr = Abase + (uint32_t)(row << 7) + (uint32_t)(((kseg ^ (row & 7)) << 4));
                LDMX4(afr[mt], addr);
            }
            uint32_t bfr[2][4];
#pragma unroll
            for (int np = 0; np < 2; np++) {
                int row = wn * 32 + np * 16 + (g >> 1) * 8 + lr;
                int kseg = ks * 2 + (g & 1);
                uint32_t addr = Bbase + (uint32_t)(row << 7) + (uint32_t)(((kseg ^ (row & 7)) << 4));
                LDMX4(bfr[np], addr);
            }
#pragma unroll
            for (int mt = 0; mt < 4; mt++)
#pragma unroll
                for (int nt = 0; nt < 4; nt++) {
                    const uint32_t* bp = &bfr[nt >> 1][(nt & 1) * 2];
                    mma16816(acc[mt][nt], afr[mt], bp[0], bp[1]);
                }
        }
    };

    load_chunk(0, 0);
    load_chunk(1, 1);
    for (int i = 0; i < kch; i++) {
        if (i + 1 < kch) cpa_wait<1>(); else cpa_wait<0>();
        __syncthreads();
        if (i + 2 < kch) load_chunk(i + 2, (i + 2) % 3);
        compute(i % 3);
    }

    const int quad = lane >> 2, tq = lane & 3;
#pragma unroll
    for (int mt = 0; mt < 4; mt++) {
        int mr0 = m0 + wm * 64 + mt * 16 + quad;
#pragma unroll
        for (int half = 0; half < 2; half++) {
            int m = mr0 + half * 8;
            if (m >= Mlim) continue;
#pragma unroll
            for (int nt = 0; nt < 4; nt++) {
                int n = n0 + wn * 32 + nt * 8 + tq * 2;
                float v0 = acc[mt][nt][half * 2 + 0] + biasI[n];
                float v1 = acc[mt][nt][half * 2 + 1] + biasI[n + 1];
                if (sel == 2) {
                    __half* crow = g_encWe16 + (size_t)m * HDIM;
                    crow[n] = __float2half(v0);
                    crow[n + 1] = __float2half(v1);
                } else {
                    float* crow = C + (size_t)m * ldc;
                    crow[n] = v0;
                    crow[n + 1] = v1;
                }
            }
        }
    }
}

// ---------------- fused encoder step: fp16 gates GEMM (64x32xK512) + LSTM ----------------
__global__ void __launch_bounds__(256, 1) enc_step16(int t) {
    extern __shared__ char sm[];
    const uint32_t Ab = smem_u32(sm);
    const uint32_t Bb = Ab + 65536;
    float* gsm = (float*)(sm + 65536 + 32768);   // [64][33]
    const int tid = threadIdx.x, bid = blockIdx.x;
    const int wid = tid >> 5, lane = tid & 31;
    const int wm = wid >> 1, wn = wid & 1;

    load_AB16<8>(Ab, Bb, g_eh16[t & 1], HDIM * 2, g_We16, HDIM * 2, bid * 32, tid);

    float acc[2][4] = {{0.f, 0.f, 0.f, 0.f}, {0.f, 0.f, 0.f, 0.f}};
    mma_64x32<8>(Ab, Bb, lane, wm, wn, acc);

    const int quad = lane >> 2, tq = lane & 3;
#pragma unroll
    for (int nt = 0; nt < 2; nt++) {
        int cb = wn * 16 + nt * 8 + tq * 2;
        int r0 = wm * 16 + quad;
        gsm[r0 * 33 + cb] = acc[nt][0];
        gsm[r0 * 33 + cb + 1] = acc[nt][1];
        gsm[(r0 + 8) * 33 + cb] = acc[nt][2];
        gsm[(r0 + 8) * 33 + cb + 1] = acc[nt][3];
    }
    __syncthreads();

    const int b = tid & 63, jl = tid >> 6;
#pragma unroll
    for (int q = 0; q < 2; q++) {
        int j2 = jl + q * 4;
        int jd = bid * 8 + j2;
        float4 gv = *reinterpret_cast<const float4*>(
            &g_xprojE[((size_t)t * 64 + b) * GDIM + (size_t)jd * 4]);
        float gi = gsm[b * 33 + j2 * 4 + 0] + gv.x;
        float gf = gsm[b * 33 + j2 * 4 + 1] + gv.y;
        float gg = gsm[b * 33 + j2 * 4 + 2] + gv.z;
        float go = gsm[b * 33 + j2 * 4 + 3] + gv.w;
        int ci = b * 512 + jd;
        float cc = sigf(gf) * g_c[ci] + sigf(gi) * tanhf(gg);
        float hh = sigf(go) * tanhf(cc);
        g_c[ci] = cc;
        __half h16 = __float2half(hh);
        g_eh16[(t + 1) & 1][ci] = h16;
        g_encout16[((size_t)b * SLEN + t) * 512 + jd] = h16;
    }
}

// ---------------- decoder hWh: fp16 GEMM (64x32xK512), direct fp32 store ----------------
__global__ void __launch_bounds__(256, 1) dec_hwh16(int t) {
    extern __shared__ char sm[];
    const uint32_t Ab = smem_u32(sm);
    const uint32_t Bb = Ab + 65536;
    const int tid = threadIdx.x, bid = blockIdx.x;
    const int wid = tid >> 5, lane = tid & 31;
    const int wm = wid >> 1, wn = wid & 1;

    load_AB16<8>(Ab, Bb, g_xh16[t & 1], 1024 * 2, g_Wh16, HDIM * 2, bid * 32, tid);

    float acc[2][4] = {{0.f, 0.f, 0.f, 0.f}, {0.f, 0.f, 0.f, 0.f}};
    mma_64x32<8>(Ab, Bb, lane, wm, wn, acc);

    const int quad = lane >> 2, tq = lane & 3;
#pragma unroll
    for (int nt = 0; nt < 2; nt++) {
        int n = bid * 32 + wn * 16 + nt * 8 + tq * 2;
        int r0 = wm * 16 + quad;
        g_hwh[r0 * 512 + n] = acc[nt][0];
        g_hwh[r0 * 512 + n + 1] = acc[nt][1];
        g_hwh[(r0 + 8) * 512 + n] = acc[nt][2];
        g_hwh[(r0 + 8) * 512 + n + 1] = acc[nt][3];
    }
}

// ---------------- decoder attention (fp16 encWe / encout inputs) ----------------
__global__ void __launch_bounds__(256, 1) k_attn(const float* __restrict__ vw, int t) {
    __shared__ float hwhs[512];
    __shared__ float vws[512];
    __shared__ float sc[128];
    __shared__ float red[128];
    const int bb = blockIdx.x;
    const int tid = threadIdx.x;
    const int cur = t & 1;

    for (int i = tid; i < 512; i += 256) {
        hwhs[i] = g_hwh[bb * 512 + i];
        vws[i] = vw[i];
    }
    __syncthreads();
    int warp = tid >> 5, lane = tid & 31;
    for (int s = warp; s < SLEN; s += 8) {
        const __half2* we2 = reinterpret_cast<const __half2*>(
            &g_encWe16[((size_t)bb * SLEN + s) * 512]);
        float a = 0.0f;
        for (int j2 = lane; j2 < 256; j2 += 32) {
            float2 wf = __half22float2(we2[j2]);
            int j = j2 * 2;
            a += tanhf(hwhs[j] + wf.x) * vws[j];
            a += tanhf(hwhs[j + 1] + wf.y) * vws[j + 1];
        }
#pragma unroll
        for (int o = 16; o > 0; o >>= 1) a += __shfl_xor_sync(0xffffffffu, a, o);
        if (lane == 0) sc[s] = a;
    }
    __syncthreads();
    if (tid < SLEN) red[tid] = sc[tid];
    __syncthreads();
    for (int o = 64; o > 0; o >>= 1) {
        if (tid < o) red[tid] = fmaxf(red[tid], red[tid + o]);
        __syncthreads();
    }
    float mx = red[0];
    __syncthreads();
    float e = 0.0f;
    if (tid < SLEN) { e = expf(sc[tid] - mx); red[tid] = e; }
    __syncthreads();
    for (int o = 64; o > 0; o >>= 1) {
        if (tid < o) red[tid] += red[tid + o];
        __syncthreads();
    }
    float inv = 1.0f / red[0];
    __syncthreads();
    if (tid < SLEN) sc[tid] = e * inv;
    __syncthreads();

    float c0 = 0.0f, c1 = 0.0f;
    const __half* eo = &g_encout16[(size_t)bb * SLEN * 512];
    for (int s = 0; s < SLEN; s++) {
        float w = sc[s];
        c0 += w * __half2float(eo[s * 512 + tid]);
        c1 += w * __half2float(eo[s * 512 + tid + 256]);
    }
    __half h0 = __float2half(c0), h1 = __float2half(c1);
    g_xh16[cur][bb * 1024 + 512 + tid] = h0;
    g_xh16[cur][bb * 1024 + 512 + tid + 256] = h1;
    size_t ma = ((size_t)t * 64 + bb) * 1024;
    g_Ahf[ma + 512 + tid] = h0;
    g_Ahf[ma + 512 + tid + 256] = h1;
}

// ---------------- fused decoder gates: fp16 GEMM (64x32xK1024) + LSTM ----------------
__global__ void __launch_bounds__(256, 1) dec_gates16(int t) {
    extern __shared__ char sm[];
    const uint32_t Ab = smem_u32(sm);
    const uint32_t Bb = Ab + 131072;
    float* gsm = (float*)(sm + 131072 + 65536);   // [64][33]
    const int tid = threadIdx.x, bid = blockIdx.x;
    const int wid = tid >> 5, lane = tid & 31;
    const int wm = wid >> 1, wn = wid & 1;

    load_AB16<16>(Ab, Bb, g_xh16[t & 1], 1024 * 2, g_Wd16, 1024 * 2, bid * 32, tid);

    float acc[2][4] = {{0.f, 0.f, 0.f, 0.f}, {0.f, 0.f, 0.f, 0.f}};
    mma_64x32<16>(Ab, Bb, lane, wm, wn, acc);

    const int quad = lane >> 2, tq = lane & 3;
#pragma unroll
    for (int nt = 0; nt < 2; nt++) {
        int cb = wn * 16 + nt * 8 + tq * 2;
        int r0 = wm * 16 + quad;
        gsm[r0 * 33 + cb] = acc[nt][0];
        gsm[r0 * 33 + cb + 1] = acc[nt][1];
        gsm[(r0 + 8) * 33 + cb] = acc[nt][2];
        gsm[(r0 + 8) * 33 + cb + 1] = acc[nt][3];
    }
    __syncthreads();

    const int b = tid & 63, jl = tid >> 6;
#pragma unroll
    for (int q = 0; q < 2; q++) {
        int j2 = jl + q * 4;
        int jd = bid * 8 + j2;
        float4 gv = *reinterpret_cast<const float4*>(
            &g_decxp[((size_t)t * 64 + b) * GDIM + (size_t)jd * 4]);
        float gi = gsm[b * 33 + j2 * 4 + 0] + gv.x;
        float gf = gsm[b * 33 + j2 * 4 + 1] + gv.y;
        float gg = gsm[b * 33 + j2 * 4 + 2] + gv.z;
        float go = gsm[b * 33 + j2 * 4 + 3] + gv.w;
        int ci = b * 512 + jd;
        float cc = sigf(gf) * g_c[ci] + sigf(gi) * tanhf(gg);
        float hh = sigf(go) * tanhf(cc);
        g_c[ci] = cc;
        __half h16 = __float2half(hh);
        g_xh16[(t + 1) & 1][b * 1024 + jd] = h16;
        g_Ahf[((size_t)t * 64 + b) * 1024 + jd] = h16;
    }
}

// ---------------- fp16 tensor-core fc GEMM: ONE M-tile row (128 rows) x 197 N-tiles ----------------
__global__ void __launch_bounds__(256, 1) hgemm_fc(int mtile, const float* __restrict__ fc_b,
                                                   float* __restrict__ out) {
    extern __shared__ char smc[];
    const uint32_t sbase = smem_u32(smc);
    const int tid = threadIdx.x;
    const int wid = tid >> 5, lane = tid & 31;
    const int m0 = mtile * 128;
    const int n0 = blockIdx.x * 256;
    const int wm = wid >> 2;
    const int wn = wid & 3;

    const char* Ag = (const char*)g_Ahf + (size_t)m0 * (KD * 2);
    const char* Bg = (const char*)g_Bhf + (size_t)n0 * (KD * 2);

    float acc[4][8][4];
#pragma unroll
    for (int i = 0; i < 4; i++)
#pragma unroll
        for (int j = 0; j < 8; j++)
#pragma unroll
            for (int r = 0; r < 4; r++) acc[i][j][r] = 0.0f;

    auto load_chunk = [&](int kc, int slot) {
        uint32_t st = sbase + (uint32_t)slot * STGB;
#pragma unroll
        for (int i = 0; i < 12; i++) {
            int idx = tid + (i << 8);
            int isB = idx >= 1024;
            int r = (isB ? (idx - 1024) : idx) >> 3;
            int seg = idx & 7;
            uint32_t dst = st + (isB ? 16384u : 0u) + (uint32_t)(r << 7)
                         + (uint32_t)(((seg ^ (r & 7)) << 4));
            const char* src = (isB ? Bg : Ag) + (size_t)r * (KD * 2) + (size_t)kc * 128 + (seg << 4);
            cpa16(dst, src);
        }
        cpa_commit();
    };

    const int g = lane >> 3, lr = lane & 7;

    auto compute = [&](int slot) {
        uint32_t Abase = sbase + (uint32_t)slot * STGB;
        uint32_t Bbase = Abase + 16384u;
#pragma unroll
        for (int ks = 0; ks < 4; ks++) {
            uint32_t afr[4][4];
#pragma unroll
            for (int mt = 0; mt < 4; mt++) {
                int row = wm * 64 + mt * 16 + (g & 1) * 8 + lr;
                int kseg = ks * 2 + (g >> 1);
                uint32_t addr = Abase + (uint32_t)(row << 7) + (uint32_t)(((kseg ^ (row & 7)) << 4));
                LDMX4(afr[mt], addr);
            }
            uint32_t bfr[4][4];
#pragma unroll
            for (int np = 0; np < 4; np++) {
                int row = wn * 64 + np * 16 + (g >> 1) * 8 + lr;
                int kseg = ks * 2 + (g & 1);
                uint32_t addr = Bbase + (uint32_t)(row << 7) + (uint32_t)(((kseg ^ (row & 7)) << 4));
                LDMX4(bfr[np], addr);
            }
#pragma unroll
            for (int mt = 0; mt < 4; mt++)
#pragma unroll
                for (int nt = 0; nt < 8; nt++) {
                    const uint32_t* bp = &bfr[nt >> 1][(nt & 1) * 2];
                    mma16816(acc[mt][nt], afr[mt], bp[0], bp[1]);
                }
        }
    };

    load_chunk(0, 0);
    load_chunk(1, 1);
    for (int i = 0; i < NCHK; i++) {
        if (i + 1 < NCHK) cpa_wait<1>(); else cpa_wait<0>();
        __syncthreads();
        if (i + 2 < NCHK) load_chunk(i + 2, (i + 2) % 3);
        compute(i % 3);
    }

    const int quad = lane >> 2, tq = lane & 3;
#pragma unroll
    for (int mt = 0; mt < 4; mt++) {
        int mr0 = m0 + wm * 64 + mt * 16 + quad;
#pragma unroll
        for (int half = 0; half < 2; half++) {
            int m = mr0 + half * 8;
            if (m >= TD * BATCH) continue;
            int bb = m & 63, tt = m >> 6;
            float* orow = out + ((size_t)bb * TLEN + (tt + 1)) * VCAB;
#pragma unroll
            for (int nt = 0; nt < 8; nt++) {
                int n = n0 + wn * 64 + nt * 8 + tq * 2;
                float v0 = acc[mt][nt][half * 2 + 0];
                float v1 = acc[mt][nt][half * 2 + 1];
                if (n < VCAB)     orow[n]     = v0 + fc_b[n];
                if (n + 1 < VCAB) orow[n + 1] = v1 + fc_b[n + 1];
            }
        }
    }
}

// ---------------- host driver ----------------
extern "C" void kernel_launch(void* const* d_in, const int* in_sizes, int n_in,
                              void* d_out, int out_size) {
    const int*   src     = (const int*)  d_in[0];
    const int*   trg     = (const int*)  d_in[1];
    const float* enc_emb = (const float*)d_in[2];
    const float* enc_Wih = (const float*)d_in[3];
    const float* enc_Whh = (const float*)d_in[4];
    const float* enc_bih = (const float*)d_in[5];
    const float* enc_bhh = (const float*)d_in[6];
    const float* dec_emb = (const float*)d_in[7];
    const float* dec_Wih = (const float*)d_in[8];
    const float* dec_Whh = (const float*)d_in[9];
    const float* dec_bih = (const float*)d_in[10];
    const float* dec_bhh = (const float*)d_in[11];
    const float* attn_W  = (const float*)d_in[12];
    const float* attn_b  = (const float*)d_in[13];
    const float* v_w     = (const float*)d_in[14];
    const float* fc_W    = (const float*)d_in[15];
    const float* fc_b    = (const float*)d_in[16];
    float* out = (float*)d_out;
    (void)in_sizes; (void)n_in; (void)out_size;

    const int ENC_SMEM = 65536 + 32768 + 64 * 33 * 4;        // 106752
    const int HWH_SMEM = 65536 + 32768;                      // 98304
    const int DEC_SMEM = 131072 + 65536 + 64 * 33 * 4;       // 205056
    const int PROJ_SMEM = 3 * 32768;                         // 98304
    cudaFuncSetAttribute(hgemm_fc, cudaFuncAttributeMaxDynamicSharedMemorySize, 3 * STGB);
    cudaFuncSetAttribute(hgemm_proj, cudaFuncAttributeMaxDynamicSharedMemorySize, PROJ_SMEM);
    cudaFuncSetAttribute(enc_step16, cudaFuncAttributeMaxDynamicSharedMemorySize, ENC_SMEM);
    cudaFuncSetAttribute(dec_hwh16, cudaFuncAttributeMaxDynamicSharedMemorySize, HWH_SMEM);
    cudaFuncSetAttribute(dec_gates16, cudaFuncAttributeMaxDynamicSharedMemorySize, DEC_SMEM);

    // side stream (lowest priority) + fork-join events (capture-legal pattern)
    int prLo = 0, prHi = 0;
    cudaDeviceGetStreamPriorityRange(&prLo, &prHi);
    cudaStream_t s2;
    cudaStreamCreateWithPriority(&s2, cudaStreamNonBlocking, prLo);
    cudaEvent_t evRoot, evDone, evT[32];
    cudaEventCreateWithFlags(&evRoot, cudaEventDisableTiming);
    cudaEventCreateWithFlags(&evDone, cudaEventDisableTiming);
    for (int i = 0; i < 32; i++) cudaEventCreateWithFlags(&evT[i], cudaEventDisableTiming);

    // ---- setup on main stream ----
    k_biasI<<<8, 256>>>(enc_bih, enc_bhh, dec_bih, dec_bhh);
    k_w16_enc<<<(int)(((size_t)GDIM * HDIM + 255) / 256), 256>>>(enc_Whh);
    k_w16_dec<<<(int)(((size_t)GDIM * 1024 + 255) / 256), 256>>>(dec_Wih, dec_Whh);
    k_w16_attn<<<(int)(((size_t)HDIM * HDIM + 255) / 256), 256>>>(attn_W);
    k_w16_wih<<<(int)(((size_t)GDIM * EDIM + 255) / 256), 256>>>(enc_Wih, dec_Wih);
    k_gather_enc<<<SLEN * BATCH, EDIM>>>(enc_emb, src);
    k_gather_dec<<<TD * BATCH, EDIM>>>(dec_emb, trg);
    k_zero_state<<<(BATCH * HDIM + 255) / 256, 256>>>();

    // fork: side stream does out-zeroing, fc B conversion, decoder input projection
    cudaEventRecord(evRoot, 0);
    cudaStreamWaitEvent(s2, evRoot, 0);
    k_zero_out<<<(int)(((size_t)BATCH * VCAB + 255) / 256), 256, 0, s2>>>(out);
    k_convB_h<<<(int)(((size_t)VCAB * KD / 4 + 255) / 256), 256, 0, s2>>>(fc_W);
    hgemm_proj<<<dim3(MPAD / 128, GDIM / 128), 256, PROJ_SMEM, s2>>>(1, nullptr);

    // main stream: encoder input projection + encoder recurrence
    hgemm_proj<<<dim3((SLEN * BATCH) / 128, GDIM / 128), 256, PROJ_SMEM>>>(0, nullptr);
    for (int t = 0; t < SLEN; t++)
        enc_step16<<<64, 256, ENC_SMEM>>>(t);

    // encWe = enc_out @ attn_W[:, H:]^T + attn_b (fp16 mma, fp16 output)
    hgemm_proj<<<dim3((SLEN * BATCH) / 128, HDIM / 128), 256, PROJ_SMEM>>>(2, attn_b);

    k_init_dec<<<128, 256>>>();

    // decoder: 3 kernels/step; after each odd step, release the corresponding fc M-tile
    // on the low-priority side stream (fc tile m covers t = 2m, 2m+1).
    for (int t = 0; t < TD; t++) {
        dec_hwh16<<<16, 256, HWH_SMEM>>>(t);
        k_attn<<<64, 256>>>(v_w, t);
        dec_gates16<<<64, 256, DEC_SMEM>>>(t);
        if ((t & 1) == 1) {
            int m = t >> 1;                      // 0..30
            cudaEventRecord(evT[m], 0);
            cudaStreamWaitEvent(s2, evT[m], 0);
            hgemm_fc<<<NPAD / 256, 256, 3 * STGB, s2>>>(m, fc_b, out);
        }
    }
    // last tile (t = 62 + zero pad rows)
    cudaEventRecord(evT[31], 0);
    cudaStreamWaitEvent(s2, evT[31], 0);
    hgemm_fc<<<NPAD / 256, 256, 3 * STGB, s2>>>(31, fc_b, out);

    // join side stream back into main stream before returning
    cudaEventRecord(evDone, s2);
    cudaStreamWaitEvent((cudaStream_t)0, evDone, 0);
}

// round 14
// speedup vs baseline: 1.0751x; 1.0751x over previous
#include <cuda_runtime.h>
#include <cuda_fp16.h>
#include <math.h>
#include <stdint.h>

#define VCAB 50257
#define EDIM 256
#define HDIM 512
#define BATCH 64
#define SLEN 128
#define TLEN 64
#define TD 63            // decoder steps (T-1)
#define GDIM 2048        // 4*H

// fc GEMM dims (fp16 mma.sync path)
#define KD 1024
#define MPAD 4096
#define NPAD 50432       // 197 * 256
#define NCHK 16          // KD / 64
#define STGB 49152       // fc stage bytes: A 16KB + B 32KB

// ---------------- scratch (static device allocations; no cudaMalloc) ----------------
__device__ __align__(16) float g_bIenc[GDIM];
__device__ __align__(16) float g_bIdec[GDIM];
__device__ __align__(16) float g_xprojE[(size_t)SLEN * BATCH * GDIM];  // INTERLEAVED [m][j*4+g]
__device__ __align__(16) float g_decxp[(size_t)MPAD * GDIM];           // INTERLEAVED
__device__ __align__(16) float g_c[BATCH * HDIM];
__device__ __align__(16) float g_hwh[BATCH * HDIM];
__device__ __align__(16) float g_hwp[(size_t)64 * BATCH * HDIM];       // hWh partials [kz][b][n]
// fp16 embeddings / states
__device__ __align__(16) __half g_encX16[(size_t)SLEN * BATCH * EDIM];
__device__ __align__(16) __half g_decX16[(size_t)MPAD * EDIM];
__device__ __align__(16) __half g_encout16[(size_t)BATCH * SLEN * HDIM];
__device__ __align__(16) __half g_encWe16[(size_t)BATCH * SLEN * HDIM];
__device__ __align__(16) __half g_eh16[2][BATCH * HDIM];
__device__ __align__(16) __half g_xh16[2][BATCH * 1024];
// fp16 gate-interleaved weights
__device__ __align__(16) __half g_We16[(size_t)GDIM * HDIM];
__device__ __align__(16) __half g_Wd16[(size_t)GDIM * 1024];
__device__ __align__(16) __half g_WihE16[(size_t)GDIM * EDIM];
__device__ __align__(16) __half g_WihD16[(size_t)GDIM * EDIM];
// attention weights [n][k]
__device__ __align__(16) __half g_Wh16[(size_t)HDIM * HDIM];
__device__ __align__(16) __half g_Wat16[(size_t)HDIM * HDIM];
// fp16 operands for the tensor-core fc GEMM (pad rows stay zero: never written)
__device__ __align__(16) __half g_Ahf[(size_t)MPAD * KD];
__device__ __align__(16) __half g_Bhf[(size_t)NPAD * KD];

__device__ __forceinline__ float sigf(float x) { return 1.0f / (1.0f + expf(-x)); }

// ---------------- PTX helpers (compute_103-safe) ----------------
__device__ __forceinline__ uint32_t smem_u32(const void* p) {
    uint32_t a;
    asm("{ .reg .u64 t; cvta.to.shared.u64 t, %1; cvt.u32.u64 %0, t; }" : "=r"(a) : "l"(p));
    return a;
}
__device__ __forceinline__ void cpa16(uint32_t dst, const void* src) {
    asm volatile("cp.async.cg.shared.global [%0], [%1], 16;" :: "r"(dst), "l"(src) : "memory");
}
__device__ __forceinline__ void cpa_commit() { asm volatile("cp.async.commit_group;" ::: "memory"); }
template <int N> __device__ __forceinline__ void cpa_wait() {
    asm volatile("cp.async.wait_group %0;" :: "n"(N) : "memory");
}
#define LDMX4(r, addr) \
    asm volatile("ldmatrix.sync.aligned.m8n8.x4.shared.b16 {%0,%1,%2,%3}, [%4];" \
        : "=r"((r)[0]), "=r"((r)[1]), "=r"((r)[2]), "=r"((r)[3]) : "r"(addr))
__device__ __forceinline__ void mma16816(float* c, const uint32_t* a, uint32_t b0, uint32_t b1) {
    asm volatile("mma.sync.aligned.m16n8k16.row.col.f32.f16.f16.f32 "
        "{%0,%1,%2,%3}, {%4,%5,%6,%7}, {%8,%9}, {%0,%1,%2,%3};"
        : "+f"(c[0]), "+f"(c[1]), "+f"(c[2]), "+f"(c[3])
        : "r"(a[0]), "r"(a[1]), "r"(a[2]), "r"(a[3]), "r"(b0), "r"(b1));
}

// ---------------- setup kernels ----------------
__global__ void k_biasI(const float* __restrict__ ebih, const float* __restrict__ ebhh,
                        const float* __restrict__ dbih, const float* __restrict__ dbhh) {
    int n = blockIdx.x * blockDim.x + threadIdx.x;
    if (n < GDIM) {
        int j = n >> 2, g = n & 3;
        int r = g * 512 + j;
        g_bIenc[n] = ebih[r] + ebhh[r];
        g_bIdec[n] = dbih[r] + dbhh[r];
    }
}

__global__ void k_w16_enc(const float* __restrict__ Whh) {
    size_t idx = (size_t)blockIdx.x * blockDim.x + threadIdx.x;
    if (idx >= (size_t)GDIM * HDIM) return;
    int n = (int)(idx >> 9);
    int k = (int)(idx & 511);
    int j = n >> 2, g = n & 3;
    g_We16[idx] = __float2half(Whh[(size_t)(g * 512 + j) * 512 + k]);
}

__global__ void k_w16_dec(const float* __restrict__ dWih, const float* __restrict__ dWhh) {
    size_t idx = (size_t)blockIdx.x * blockDim.x + threadIdx.x;
    if (idx >= (size_t)GDIM * 1024) return;
    int n = (int)(idx >> 10);
    int k = (int)(idx & 1023);
    int j = n >> 2, g = n & 3;
    int row = g * 512 + j;
    float v = (k < 512) ? dWhh[(size_t)row * 512 + k]
                        : dWih[(size_t)row * (EDIM + HDIM) + EDIM + (k - 512)];
    g_Wd16[idx] = __float2half(v);
}

__global__ void k_w16_attn(const float* __restrict__ attnW) {
    size_t idx = (size_t)blockIdx.x * blockDim.x + threadIdx.x;
    if (idx >= (size_t)HDIM * HDIM) return;
    int n = (int)(idx >> 9);
    int k = (int)(idx & 511);
    g_Wh16[idx] = __float2half(attnW[(size_t)n * 1024 + k]);
    g_Wat16[idx] = __float2half(attnW[(size_t)n * 1024 + 512 + k]);
}

__global__ void k_w16_wih(const float* __restrict__ eWih, const float* __restrict__ dWih) {
    size_t idx = (size_t)blockIdx.x * blockDim.x + threadIdx.x;
    if (idx >= (size_t)GDIM * EDIM) return;
    int n = (int)(idx >> 8);
    int k = (int)(idx & 255);
    int j = n >> 2, g = n & 3;
    int row = g * 512 + j;
    g_WihE16[idx] = __float2half(eWih[(size_t)row * EDIM + k]);
    g_WihD16[idx] = __float2half(dWih[(size_t)row * (EDIM + HDIM) + k]);
}

__global__ void k_gather_enc(const float* __restrict__ emb, const int* __restrict__ src) {
    int m = blockIdx.x;
    int e = threadIdx.x;
    int s = m >> 6, b = m & 63;
    int tok = src[b * SLEN + s];
    g_encX16[(size_t)m * EDIM + e] = __float2half(emb[(size_t)tok * EDIM + e]);
}

__global__ void k_gather_dec(const float* __restrict__ emb, const int* __restrict__ trg) {
    int m = blockIdx.x;
    int e = threadIdx.x;
    int t = m >> 6, b = m & 63;
    int tok = trg[b * TLEN + t];
    g_decX16[(size_t)m * EDIM + e] = __float2half(emb[(size_t)tok * EDIM + e]);
}

__global__ void k_zero_out(float* __restrict__ out) {
    size_t idx = (size_t)blockIdx.x * blockDim.x + threadIdx.x;
    if (idx >= (size_t)BATCH * VCAB) return;
    size_t b = idx / VCAB, v = idx % VCAB;
    out[b * (size_t)TLEN * VCAB + v] = 0.0f;
}

__global__ void k_zero_state() {
    int i = blockIdx.x * blockDim.x + threadIdx.x;
    if (i < BATCH * HDIM) {
        g_eh16[0][i] = __float2half(0.0f);
        g_c[i] = 0.0f;
    }
}

__global__ void k_init_dec() {
    int i = blockIdx.x * blockDim.x + threadIdx.x;
    int b = i >> 9, j = i & 511;
    g_xh16[0][b * 1024 + j] = g_eh16[0][b * 512 + j];
}

__global__ void k_convB_h(const float* __restrict__ W) {
    size_t i4 = (size_t)blockIdx.x * blockDim.x + threadIdx.x;
    if (i4 * 4 >= (size_t)VCAB * KD) return;
    float4 v = *reinterpret_cast<const float4*>(W + i4 * 4);
    __half2* dst = reinterpret_cast<__half2*>(g_Bhf + i4 * 4);
    dst[0] = __floats2half2_rn(v.x, v.y);
    dst[1] = __floats2half2_rn(v.z, v.w);
}

// ============ shared fp16 GEMM tile machinery ============
template <int NCH>
__device__ __forceinline__ void load_AB16(uint32_t Ab, uint32_t Bb,
                                          const __half* __restrict__ Aglob, int apitchB,
                                          const __half* __restrict__ Bglob, int bpitchB,
                                          int n0, int tid) {
    for (int i = tid; i < 64 * 8 * NCH; i += 256) {
        int kc = i >> 9, rem = i & 511;
        int r = rem >> 3, s = rem & 7;
        uint32_t dst = Ab + kc * 8192 + (r << 7) + (((s ^ (r & 7)) << 4));
        const char* src = (const char*)Aglob + (size_t)r * apitchB + kc * 128 + (s << 4);
        cpa16(dst, src);
    }
    for (int i = tid; i < 32 * 8 * NCH; i += 256) {
        int kc = i >> 8, rem = i & 255;
        int r = rem >> 3, s = rem & 7;
        uint32_t dst = Bb + kc * 4096 + (r << 7) + (((s ^ (r & 7)) << 4));
        const char* src = (const char*)Bglob + (size_t)(n0 + r) * bpitchB + kc * 128 + (s << 4);
        cpa16(dst, src);
    }
    cpa_commit();
    cpa_wait<0>();
    __syncthreads();
}

template <int NCH>
__device__ __forceinline__ void mma_64x32(uint32_t Ab, uint32_t Bb, int lane, int wm, int wn,
                                          float acc[2][4]) {
    const int g = lane >> 3, lr = lane & 7;
    for (int kc = 0; kc < NCH; kc++) {
#pragma unroll
        for (int ks = 0; ks < 4; ks++) {
            uint32_t afr[4], bfr[4];
            {
                int row = wm * 16 + (g & 1) * 8 + lr;
                int kseg = ks * 2 + (g >> 1);
                uint32_t addr = Ab + kc * 8192 + (row << 7) + (((kseg ^ (row & 7)) << 4));
                LDMX4(afr, addr);
            }
            {
                int row = wn * 16 + (g >> 1) * 8 + lr;
                int kseg = ks * 2 + (g & 1);
                uint32_t addr = Bb + kc * 4096 + (row << 7) + (((kseg ^ (row & 7)) << 4));
                LDMX4(bfr, addr);
            }
            mma16816(acc[0], afr, bfr[0], bfr[1]);
            mma16816(acc[1], afr, bfr[2], bfr[3]);
        }
    }
}

// ---------------- fp16 projection GEMM (generalized): C = A @ B^T + bias ----------------
// sel 0: encoder xproj (K=256) | sel 1: decoder xproj (K=256) | sel 2: encWe (K=512, fp16 out)
__global__ void __launch_bounds__(256, 1) hgemm_proj(int sel, const float* __restrict__ bias_ext) {
    const __half* A;
    const __half* B;
    const float* biasI;
    float* C = nullptr;
    int Mlim, ldc, kch, kpitch;
    if (sel == 0) {
        A = g_encX16; B = g_WihE16; biasI = g_bIenc; C = g_xprojE;
        Mlim = SLEN * BATCH; ldc = GDIM; kch = 4; kpitch = EDIM * 2;
    } else if (sel == 1) {
        A = g_decX16; B = g_WihD16; biasI = g_bIdec; C = g_decxp;
        Mlim = TD * BATCH; ldc = GDIM; kch = 4; kpitch = EDIM * 2;
    } else {
        A = g_encout16; B = g_Wat16; biasI = bias_ext;
        Mlim = SLEN * BATCH; ldc = HDIM; kch = 8; kpitch = HDIM * 2;
    }

    extern __shared__ char smc[];
    const uint32_t sbase = smem_u32(smc);
    const int tid = threadIdx.x;
    const int wid = tid >> 5, lane = tid & 31;
    const int m0 = blockIdx.x * 128;
    const int n0 = blockIdx.y * 128;
    const int wm = wid >> 2, wn = wid & 3;

    const char* Ag = (const char*)A + (size_t)m0 * kpitch;
    const char* Bg = (const char*)B + (size_t)n0 * kpitch;

    float acc[4][4][4];
#pragma unroll
    for (int i = 0; i < 4; i++)
#pragma unroll
        for (int j = 0; j < 4; j++)
#pragma unroll
            for (int r = 0; r < 4; r++) acc[i][j][r] = 0.0f;

    auto load_chunk = [&](int kc, int slot) {
        uint32_t st = sbase + (uint32_t)slot * 32768;
#pragma unroll
        for (int i = 0; i < 8; i++) {
            int idx = tid + (i << 8);
            int isB = idx >> 10;
            int r = (idx & 1023) >> 3;
            int seg = idx & 7;
            uint32_t dst = st + (isB ? 16384u : 0u) + (uint32_t)(r << 7)
                         + (uint32_t)(((seg ^ (r & 7)) << 4));
            const char* src = (isB ? Bg : Ag) + (size_t)r * kpitch + (size_t)kc * 128 + (seg << 4);
            cpa16(dst, src);
        }
        cpa_commit();
    };

    const int g = lane >> 3, lr = lane & 7;
    auto compute = [&](int slot) {
        uint32_t Abase = sbase + (uint32_t)slot * 32768;
        uint32_t Bbase = Abase + 16384u;
#pragma unroll
        for (int ks = 0; ks < 4; ks++) {
            uint32_t afr[4][4];
#pragma unroll
            for (int mt = 0; mt < 4; mt++) {
                int row = wm * 64 + mt * 16 + (g & 1) * 8 + lr;
                int kseg = ks * 2 + (g >> 1);
                uint32_t addr = Abase + (uint32_t)(row << 7) + (uint32_t)(((kseg ^ (row & 7)) << 4));
                LDMX4(afr[mt], addr);
            }
            uint32_t bfr[2][4];
#pragma unroll
            for (int np = 0; np < 2; np++) {
                int row = wn * 32 + np * 16 + (g >> 1) * 8 + lr;
                int kseg = ks * 2 + (g & 1);
                uint32_t addr = Bbase + (uint32_t)(row << 7) + (uint32_t)(((kseg ^ (row & 7)) << 4));
                LDMX4(bfr[np], addr);
            }
#pragma unroll
            for (int mt = 0; mt < 4; mt++)
#pragma unroll
                for (int nt = 0; nt < 4; nt++) {
                    const uint32_t* bp = &bfr[nt >> 1][(nt & 1) * 2];
                    mma16816(acc[mt][nt], afr[mt], bp[0], bp[1]);
                }
        }
    };

    load_chunk(0, 0);
    load_chunk(1, 1);
    for (int i = 0; i < kch; i++) {
        if (i + 1 < kch) cpa_wait<1>(); else cpa_wait<0>();
        __syncthreads();
        if (i + 2 < kch) load_chunk(i + 2, (i + 2) % 3);
        compute(i % 3);
    }

    const int quad = lane >> 2, tq = lane & 3;
#pragma unroll
    for (int mt = 0; mt < 4; mt++) {
        int mr0 = m0 + wm * 64 + mt * 16 + quad;
#pragma unroll
        for (int half = 0; half < 2; half++) {
            int m = mr0 + half * 8;
            if (m >= Mlim) continue;
#pragma unroll
            for (int nt = 0; nt < 4; nt++) {
                int n = n0 + wn * 32 + nt * 8 + tq * 2;
                float v0 = acc[mt][nt][half * 2 + 0] + biasI[n];
                float v1 = acc[mt][nt][half * 2 + 1] + biasI[n + 1];
                if (sel == 2) {
                    __half* crow = g_encWe16 + (size_t)m * HDIM;
                    crow[n] = __float2half(v0);
                    crow[n + 1] = __float2half(v1);
                } else {
                    float* crow = C + (size_t)m * ldc;
                    crow[n] = v0;
                    crow[n + 1] = v1;
                }
            }
        }
    }
}

// ---------------- fused encoder step: fp16 gates GEMM (64x32xK512) + LSTM ----------------
__global__ void __launch_bounds__(256, 1) enc_step16(int t) {
    extern __shared__ char sm[];
    const uint32_t Ab = smem_u32(sm);
    const uint32_t Bb = Ab + 65536;
    float* gsm = (float*)(sm + 65536 + 32768);   // [64][33]
    const int tid = threadIdx.x, bid = blockIdx.x;
    const int wid = tid >> 5, lane = tid & 31;
    const int wm = wid >> 1, wn = wid & 1;

    load_AB16<8>(Ab, Bb, g_eh16[t & 1], HDIM * 2, g_We16, HDIM * 2, bid * 32, tid);

    float acc[2][4] = {{0.f, 0.f, 0.f, 0.f}, {0.f, 0.f, 0.f, 0.f}};
    mma_64x32<8>(Ab, Bb, lane, wm, wn, acc);

    const int quad = lane >> 2, tq = lane & 3;
#pragma unroll
    for (int nt = 0; nt < 2; nt++) {
        int cb = wn * 16 + nt * 8 + tq * 2;
        int r0 = wm * 16 + quad;
        gsm[r0 * 33 + cb] = acc[nt][0];
        gsm[r0 * 33 + cb + 1] = acc[nt][1];
        gsm[(r0 + 8) * 33 + cb] = acc[nt][2];
        gsm[(r0 + 8) * 33 + cb + 1] = acc[nt][3];
    }
    __syncthreads();

    const int b = tid & 63, jl = tid >> 6;
#pragma unroll
    for (int q = 0; q < 2; q++) {
        int j2 = jl + q * 4;
        int jd = bid * 8 + j2;
        float4 gv = *reinterpret_cast<const float4*>(
            &g_xprojE[((size_t)t * 64 + b) * GDIM + (size_t)jd * 4]);
        float gi = gsm[b * 33 + j2 * 4 + 0] + gv.x;
        float gf = gsm[b * 33 + j2 * 4 + 1] + gv.y;
        float gg = gsm[b * 33 + j2 * 4 + 2] + gv.z;
        float go = gsm[b * 33 + j2 * 4 + 3] + gv.w;
        int ci = b * 512 + jd;
        float cc = sigf(gf) * g_c[ci] + sigf(gi) * tanhf(gg);
        float hh = sigf(go) * tanhf(cc);
        g_c[ci] = cc;
        __half h16 = __float2half(hh);
        g_eh16[(t + 1) & 1][ci] = h16;
        g_encout16[((size_t)b * SLEN + t) * 512 + jd] = h16;
    }
}

// ---------------- decoder hWh (used ONCE for t=0): fp16 GEMM (64x32xK512) ----------------
__global__ void __launch_bounds__(256, 1) dec_hwh16(int t) {
    extern __shared__ char sm[];
    const uint32_t Ab = smem_u32(sm);
    const uint32_t Bb = Ab + 65536;
    const int tid = threadIdx.x, bid = blockIdx.x;
    const int wid = tid >> 5, lane = tid & 31;
    const int wm = wid >> 1, wn = wid & 1;

    load_AB16<8>(Ab, Bb, g_xh16[t & 1], 1024 * 2, g_Wh16, HDIM * 2, bid * 32, tid);

    float acc[2][4] = {{0.f, 0.f, 0.f, 0.f}, {0.f, 0.f, 0.f, 0.f}};
    mma_64x32<8>(Ab, Bb, lane, wm, wn, acc);

    const int quad = lane >> 2, tq = lane & 3;
#pragma unroll
    for (int nt = 0; nt < 2; nt++) {
        int n = bid * 32 + wn * 16 + nt * 8 + tq * 2;
        int r0 = wm * 16 + quad;
        g_hwh[r0 * 512 + n] = acc[nt][0];
        g_hwh[r0 * 512 + n + 1] = acc[nt][1];
        g_hwh[(r0 + 8) * 512 + n] = acc[nt][2];
        g_hwh[(r0 + 8) * 512 + n + 1] = acc[nt][3];
    }
}

// ---------------- decoder attention ----------------
// t==0: hwh from g_hwh (seeded by dec_hwh16); t>0: reduce 64 split-K partials from g_hwp.
__global__ void __launch_bounds__(256, 1) k_attn(const float* __restrict__ vw, int t) {
    __shared__ float hwhs[512];
    __shared__ float vws[512];
    __shared__ float sc[128];
    __shared__ float red[128];
    const int bb = blockIdx.x;
    const int tid = threadIdx.x;
    const int cur = t & 1;

    if (t == 0) {
        for (int i = tid; i < 512; i += 256) {
            hwhs[i] = g_hwh[bb * 512 + i];
            vws[i] = vw[i];
        }
    } else {
        for (int i = tid; i < 512; i += 256) {
            float s = 0.0f;
#pragma unroll
            for (int kz = 0; kz < 64; kz++)
                s += g_hwp[((size_t)kz * 64 + bb) * 512 + i];
            hwhs[i] = s;
            vws[i] = vw[i];
        }
    }
    __syncthreads();
    int warp = tid >> 5, lane = tid & 31;
    for (int s = warp; s < SLEN; s += 8) {
        const __half2* we2 = reinterpret_cast<const __half2*>(
            &g_encWe16[((size_t)bb * SLEN + s) * 512]);
        float a = 0.0f;
        for (int j2 = lane; j2 < 256; j2 += 32) {
            float2 wf = __half22float2(we2[j2]);
            int j = j2 * 2;
            a += tanhf(hwhs[j] + wf.x) * vws[j];
            a += tanhf(hwhs[j + 1] + wf.y) * vws[j + 1];
        }
#pragma unroll
        for (int o = 16; o > 0; o >>= 1) a += __shfl_xor_sync(0xffffffffu, a, o);
        if (lane == 0) sc[s] = a;
    }
    __syncthreads();
    if (tid < SLEN) red[tid] = sc[tid];
    __syncthreads();
    for (int o = 64; o > 0; o >>= 1) {
        if (tid < o) red[tid] = fmaxf(red[tid], red[tid + o]);
        __syncthreads();
    }
    float mx = red[0];
    __syncthreads();
    float e = 0.0f;
    if (tid < SLEN) { e = expf(sc[tid] - mx); red[tid] = e; }
    __syncthreads();
    for (int o = 64; o > 0; o >>= 1) {
        if (tid < o) red[tid] += red[tid + o];
        __syncthreads();
    }
    float inv = 1.0f / red[0];
    __syncthreads();
    if (tid < SLEN) sc[tid] = e * inv;
    __syncthreads();

    float c0 = 0.0f, c1 = 0.0f;
    const __half* eo = &g_encout16[(size_t)bb * SLEN * 512];
    for (int s = 0; s < SLEN; s++) {
        float w = sc[s];
        c0 += w * __half2float(eo[s * 512 + tid]);
        c1 += w * __half2float(eo[s * 512 + tid + 256]);
    }
    __half h0 = __float2half(c0), h1 = __float2half(c1);
    g_xh16[cur][bb * 1024 + 512 + tid] = h0;
    g_xh16[cur][bb * 1024 + 512 + tid + 256] = h1;
    size_t ma = ((size_t)t * 64 + bb) * 1024;
    g_Ahf[ma + 512 + tid] = h0;
    g_Ahf[ma + 512 + tid + 256] = h1;
}

// ---------------- fused decoder gates: fp16 GEMM (64x32xK1024) + LSTM + hWh partials ----------------
// Block bid owns j-dims [bid*8, bid*8+8). After the cell update, it also emits the
// split-K hWh partial for step t+1: g_hwp[bid][b][n] = sum_{k in slice} h[b][k]*Wh[n][k].
__global__ void __launch_bounds__(256, 1) dec_gates16(int t) {
    extern __shared__ char sm[];
    const uint32_t Ab = smem_u32(sm);
    const uint32_t Bb = Ab + 131072;
    float* gsm = (float*)(sm + 131072 + 65536);     // [64][33]
    float* hs = gsm + 64 * 33;                      // [64][8] h slice
    const int tid = threadIdx.x, bid = blockIdx.x;
    const int wid = tid >> 5, lane = tid & 31;
    const int wm = wid >> 1, wn = wid & 1;

    load_AB16<16>(Ab, Bb, g_xh16[t & 1], 1024 * 2, g_Wd16, 1024 * 2, bid * 32, tid);

    float acc[2][4] = {{0.f, 0.f, 0.f, 0.f}, {0.f, 0.f, 0.f, 0.f}};
    mma_64x32<16>(Ab, Bb, lane, wm, wn, acc);

    const int quad = lane >> 2, tq = lane & 3;
#pragma unroll
    for (int nt = 0; nt < 2; nt++) {
        int cb = wn * 16 + nt * 8 + tq * 2;
        int r0 = wm * 16 + quad;
        gsm[r0 * 33 + cb] = acc[nt][0];
        gsm[r0 * 33 + cb + 1] = acc[nt][1];
        gsm[(r0 + 8) * 33 + cb] = acc[nt][2];
        gsm[(r0 + 8) * 33 + cb + 1] = acc[nt][3];
    }
    __syncthreads();

    const int b = tid & 63, jl = tid >> 6;
#pragma unroll
    for (int q = 0; q < 2; q++) {
        int j2 = jl + q * 4;
        int jd = bid * 8 + j2;
        float4 gv = *reinterpret_cast<const float4*>(
            &g_decxp[((size_t)t * 64 + b) * GDIM + (size_t)jd * 4]);
        float gi = gsm[b * 33 + j2 * 4 + 0] + gv.x;
        float gf = gsm[b * 33 + j2 * 4 + 1] + gv.y;
        float gg = gsm[b * 33 + j2 * 4 + 2] + gv.z;
        float go = gsm[b * 33 + j2 * 4 + 3] + gv.w;
        int ci = b * 512 + jd;
        float cc = sigf(gf) * g_c[ci] + sigf(gi) * tanhf(gg);
        float hh = sigf(go) * tanhf(cc);
        g_c[ci] = cc;
        __half h16 = __float2half(hh);
        g_xh16[(t + 1) & 1][b * 1024 + jd] = h16;
        g_Ahf[((size_t)t * 64 + b) * 1024 + jd] = h16;
        hs[b * 8 + j2] = hh;
    }
    __syncthreads();

    // hWh partial for step t+1: thread (b2 = tid&63, nh = tid>>6) covers n in [nh*128, nh*128+128)
    {
        const int b2 = tid & 63, nh = tid >> 6;
        float hk[8];
#pragma unroll
        for (int k = 0; k < 8; k++) hk[k] = hs[b2 * 8 + k];
        float* outp = &g_hwp[((size_t)bid * 64 + b2) * 512];
        const __half* wbase = g_Wh16 + bid * 8;
#pragma unroll 4
        for (int ni = 0; ni < 128; ni++) {
            int n = nh * 128 + ni;
            uint4 wv = *reinterpret_cast<const uint4*>(wbase + (size_t)n * 512);
            const __half2* w2 = reinterpret_cast<const __half2*>(&wv);
            float a = 0.0f;
#pragma unroll
            for (int kk = 0; kk < 4; kk++) {
                float2 wf = __half22float2(w2[kk]);
                a += hk[2 * kk] * wf.x + hk[2 * kk + 1] * wf.y;
            }
            outp[n] = a;
        }
    }
}

// ---------------- fp16 tensor-core fc GEMM: tile 128M x 256N, K=1024 ----------------
__global__ void __launch_bounds__(256, 1) hgemm_fc(const float* __restrict__ fc_b,
                                                   float* __restrict__ out) {
    extern __shared__ char smc[];
    const uint32_t sbase = smem_u32(smc);
    const int tid = threadIdx.x;
    const int wid = tid >> 5, lane = tid & 31;
    const int m0 = blockIdx.x * 128;
    const int n0 = blockIdx.y * 256;
    const int wm = wid >> 2;
    const int wn = wid & 3;

    const char* Ag = (const char*)g_Ahf + (size_t)m0 * (KD * 2);
    const char* Bg = (const char*)g_Bhf + (size_t)n0 * (KD * 2);

    float acc[4][8][4];
#pragma unroll
    for (int i = 0; i < 4; i++)
#pragma unroll
        for (int j = 0; j < 8; j++)
#pragma unroll
            for (int r = 0; r < 4; r++) acc[i][j][r] = 0.0f;

    auto load_chunk = [&](int kc, int slot) {
        uint32_t st = sbase + (uint32_t)slot * STGB;
#pragma unroll
        for (int i = 0; i < 12; i++) {
            int idx = tid + (i << 8);
            int isB = idx >= 1024;
            int r = (isB ? (idx - 1024) : idx) >> 3;
            int seg = idx & 7;
            uint32_t dst = st + (isB ? 16384u : 0u) + (uint32_t)(r << 7)
                         + (uint32_t)(((seg ^ (r & 7)) << 4));
            const char* src = (isB ? Bg : Ag) + (size_t)r * (KD * 2) + (size_t)kc * 128 + (seg << 4);
            cpa16(dst, src);
        }
        cpa_commit();
    };

    const int g = lane >> 3, lr = lane & 7;

    auto compute = [&](int slot) {
        uint32_t Abase = sbase + (uint32_t)slot * STGB;
        uint32_t Bbase = Abase + 16384u;
#pragma unroll
        for (int ks = 0; ks < 4; ks++) {
            uint32_t afr[4][4];
#pragma unroll
            for (int mt = 0; mt < 4; mt++) {
                int row = wm * 64 + mt * 16 + (g & 1) * 8 + lr;
                int kseg = ks * 2 + (g >> 1);
                uint32_t addr = Abase + (uint32_t)(row << 7) + (uint32_t)(((kseg ^ (row & 7)) << 4));
                LDMX4(afr[mt], addr);
            }
            uint32_t bfr[4][4];
#pragma unroll
            for (int np = 0; np < 4; np++) {
                int row = wn * 64 + np * 16 + (g >> 1) * 8 + lr;
                int kseg = ks * 2 + (g & 1);
                uint32_t addr = Bbase + (uint32_t)(row << 7) + (uint32_t)(((kseg ^ (row & 7)) << 4));
                LDMX4(bfr[np], addr);
            }
#pragma unroll
            for (int mt = 0; mt < 4; mt++)
#pragma unroll
                for (int nt = 0; nt < 8; nt++) {
                    const uint32_t* bp = &bfr[nt >> 1][(nt & 1) * 2];
                    mma16816(acc[mt][nt], afr[mt], bp[0], bp[1]);
                }
        }
    };

    load_chunk(0, 0);
    load_chunk(1, 1);
    for (int i = 0; i < NCHK; i++) {
        if (i + 1 < NCHK) cpa_wait<1>(); else cpa_wait<0>();
        __syncthreads();
        if (i + 2 < NCHK) load_chunk(i + 2, (i + 2) % 3);
        compute(i % 3);
    }

    const int quad = lane >> 2, tq = lane & 3;
#pragma unroll
    for (int mt = 0; mt < 4; mt++) {
        int mr0 = m0 + wm * 64 + mt * 16 + quad;
#pragma unroll
        for (int half = 0; half < 2; half++) {
            int m = mr0 + half * 8;
            if (m >= TD * BATCH) continue;
            int bb = m & 63, tt = m >> 6;
            float* orow = out + ((size_t)bb * TLEN + (tt + 1)) * VCAB;
#pragma unroll
            for (int nt = 0; nt < 8; nt++) {
                int n = n0 + wn * 64 + nt * 8 + tq * 2;
                float v0 = acc[mt][nt][half * 2 + 0];
                float v1 = acc[mt][nt][half * 2 + 1];
                if (n < VCAB)     orow[n]     = v0 + fc_b[n];
                if (n + 1 < VCAB) orow[n + 1] = v1 + fc_b[n + 1];
            }
        }
    }
}

// ---------------- host driver ----------------
extern "C" void kernel_launch(void* const* d_in, const int* in_sizes, int n_in,
                              void* d_out, int out_size) {
    const int*   src     = (const int*)  d_in[0];
    const int*   trg     = (const int*)  d_in[1];
    const float* enc_emb = (const float*)d_in[2];
    const float* enc_Wih = (const float*)d_in[3];
    const float* enc_Whh = (const float*)d_in[4];
    const float* enc_bih = (const float*)d_in[5];
    const float* enc_bhh = (const float*)d_in[6];
    const float* dec_emb = (const float*)d_in[7];
    const float* dec_Wih = (const float*)d_in[8];
    const float* dec_Whh = (const float*)d_in[9];
    const float* dec_bih = (const float*)d_in[10];
    const float* dec_bhh = (const float*)d_in[11];
    const float* attn_W  = (const float*)d_in[12];
    const float* attn_b  = (const float*)d_in[13];
    const float* v_w     = (const float*)d_in[14];
    const float* fc_W    = (const float*)d_in[15];
    const float* fc_b    = (const float*)d_in[16];
    float* out = (float*)d_out;
    (void)in_sizes; (void)n_in; (void)out_size;

    const int ENC_SMEM = 65536 + 32768 + 64 * 33 * 4;                 // 106752
    const int HWH_SMEM = 65536 + 32768;                               // 98304
    const int DEC_SMEM = 131072 + 65536 + (64 * 33 + 64 * 8) * 4;     // 207104
    const int PROJ_SMEM = 3 * 32768;                                  // 98304
    cudaFuncSetAttribute(hgemm_fc, cudaFuncAttributeMaxDynamicSharedMemorySize, 3 * STGB);
    cudaFuncSetAttribute(hgemm_proj, cudaFuncAttributeMaxDynamicSharedMemorySize, PROJ_SMEM);
    cudaFuncSetAttribute(enc_step16, cudaFuncAttributeMaxDynamicSharedMemorySize, ENC_SMEM);
    cudaFuncSetAttribute(dec_hwh16, cudaFuncAttributeMaxDynamicSharedMemorySize, HWH_SMEM);
    cudaFuncSetAttribute(dec_gates16, cudaFuncAttributeMaxDynamicSharedMemorySize, DEC_SMEM);

    // setup
    k_biasI<<<8, 256>>>(enc_bih, enc_bhh, dec_bih, dec_bhh);
    k_w16_enc<<<(int)(((size_t)GDIM * HDIM + 255) / 256), 256>>>(enc_Whh);
    k_w16_dec<<<(int)(((size_t)GDIM * 1024 + 255) / 256), 256>>>(dec_Wih, dec_Whh);
    k_w16_attn<<<(int)(((size_t)HDIM * HDIM + 255) / 256), 256>>>(attn_W);
    k_w16_wih<<<(int)(((size_t)GDIM * EDIM + 255) / 256), 256>>>(enc_Wih, dec_Wih);
    k_gather_enc<<<SLEN * BATCH, EDIM>>>(enc_emb, src);
    k_gather_dec<<<TD * BATCH, EDIM>>>(dec_emb, trg);
    k_zero_out<<<(int)(((size_t)BATCH * VCAB + 255) / 256), 256>>>(out);
    k_zero_state<<<(BATCH * HDIM + 255) / 256, 256>>>();
    k_convB_h<<<(int)(((size_t)VCAB * KD / 4 + 255) / 256), 256>>>(fc_W);

    // fp16 input projections (interleaved output + bias)
    hgemm_proj<<<dim3((SLEN * BATCH) / 128, GDIM / 128), 256, PROJ_SMEM>>>(0, nullptr);
    hgemm_proj<<<dim3(MPAD / 128, GDIM / 128), 256, PROJ_SMEM>>>(1, nullptr);

    // encoder: ONE fused fp16-mma kernel per step
    for (int t = 0; t < SLEN; t++)
        enc_step16<<<64, 256, ENC_SMEM>>>(t);

    // encWe = enc_out @ attn_W[:, H:]^T + attn_b (fp16 mma, fp16 output)
    hgemm_proj<<<dim3((SLEN * BATCH) / 128, HDIM / 128), 256, PROJ_SMEM>>>(2, attn_b);

    k_init_dec<<<128, 256>>>();

    // seed hWh for t = 0 (h from encoder)
    dec_hwh16<<<16, 256, HWH_SMEM>>>(0);

    // decoder: TWO kernels per step (attention, fused gates+LSTM+hWh-partials)
    for (int t = 0; t < TD; t++) {
        k_attn<<<64, 256>>>(v_w, t);
        dec_gates16<<<64, 256, DEC_SMEM>>>(t);
    }

    // tensor-core fc GEMM (128 x 256 tiles)
    hgemm_fc<<<dim3(MPAD / 128, NPAD / 256), 256, 3 * STGB>>>(fc_b, out);
}

// round 15
// speedup vs baseline: 1.1342x; 1.0550x over previous
#include <cuda_runtime.h>
#include <cuda_fp16.h>
#include <math.h>
#include <stdint.h>

#define VCAB 50257
#define EDIM 256
#define HDIM 512
#define BATCH 64
#define SLEN 128
#define TLEN 64
#define TD 63            // decoder steps (T-1)
#define GDIM 2048        // 4*H

// fc GEMM dims (fp16 mma.sync path)
#define KD 1024
#define MPAD 4096
#define NPAD 50432       // 197 * 256
#define NCHK 16          // KD / 64
#define STGB 49152       // fc stage bytes: A 16KB + B 32KB

// ---------------- scratch (static device allocations; no cudaMalloc) ----------------
__device__ __align__(16) float g_bIenc[GDIM];
__device__ __align__(16) float g_bIdec[GDIM];
__device__ __align__(16) float g_xprojE[(size_t)SLEN * BATCH * GDIM];  // INTERLEAVED [m][j*4+g]
__device__ __align__(16) float g_decxp[(size_t)MPAD * GDIM];           // INTERLEAVED
__device__ __align__(16) float g_c[BATCH * HDIM];
__device__ __align__(16) float g_hwh[BATCH * HDIM];
// fp16 embeddings / states
__device__ __align__(16) __half g_encX16[(size_t)SLEN * BATCH * EDIM];
__device__ __align__(16) __half g_decX16[(size_t)MPAD * EDIM];
__device__ __align__(16) __half g_encout16[(size_t)BATCH * SLEN * HDIM];
__device__ __align__(16) __half g_encWe16[(size_t)BATCH * SLEN * HDIM];
__device__ __align__(16) __half g_eh16[2][BATCH * HDIM];
__device__ __align__(16) __half g_xh16[2][BATCH * 1024];
// fp16 gate-interleaved weights
__device__ __align__(16) __half g_We16[(size_t)GDIM * HDIM];
__device__ __align__(16) __half g_Wd16[(size_t)GDIM * 1024];
__device__ __align__(16) __half g_WihE16[(size_t)GDIM * EDIM];
__device__ __align__(16) __half g_WihD16[(size_t)GDIM * EDIM];
// attention weights [n][k]
__device__ __align__(16) __half g_Wh16[(size_t)HDIM * HDIM];
__device__ __align__(16) __half g_Wat16[(size_t)HDIM * HDIM];
// fp16 operands for the tensor-core fc GEMM (pad rows stay zero: never written)
__device__ __align__(16) __half g_Ahf[(size_t)MPAD * KD];
__device__ __align__(16) __half g_Bhf[(size_t)NPAD * KD];

__device__ __forceinline__ float sigf(float x) { return 1.0f / (1.0f + expf(-x)); }

// ---------------- PTX helpers (compute_103-safe) ----------------
__device__ __forceinline__ uint32_t smem_u32(const void* p) {
    uint32_t a;
    asm("{ .reg .u64 t; cvta.to.shared.u64 t, %1; cvt.u32.u64 %0, t; }" : "=r"(a) : "l"(p));
    return a;
}
__device__ __forceinline__ void cpa16(uint32_t dst, const void* src) {
    asm volatile("cp.async.cg.shared.global [%0], [%1], 16;" :: "r"(dst), "l"(src) : "memory");
}
__device__ __forceinline__ void cpa_commit() { asm volatile("cp.async.commit_group;" ::: "memory"); }
template <int N> __device__ __forceinline__ void cpa_wait() {
    asm volatile("cp.async.wait_group %0;" :: "n"(N) : "memory");
}
#define LDMX4(r, addr) \
    asm volatile("ldmatrix.sync.aligned.m8n8.x4.shared.b16 {%0,%1,%2,%3}, [%4];" \
        : "=r"((r)[0]), "=r"((r)[1]), "=r"((r)[2]), "=r"((r)[3]) : "r"(addr))
__device__ __forceinline__ void mma16816(float* c, const uint32_t* a, uint32_t b0, uint32_t b1) {
    asm volatile("mma.sync.aligned.m16n8k16.row.col.f32.f16.f16.f32 "
        "{%0,%1,%2,%3}, {%4,%5,%6,%7}, {%8,%9}, {%0,%1,%2,%3};"
        : "+f"(c[0]), "+f"(c[1]), "+f"(c[2]), "+f"(c[3])
        : "r"(a[0]), "r"(a[1]), "r"(a[2]), "r"(a[3]), "r"(b0), "r"(b1));
}
__device__ __forceinline__ void cluster_bar() {
    asm volatile("barrier.cluster.arrive.aligned;" ::: "memory");
    asm volatile("barrier.cluster.wait.aligned;" ::: "memory");
}

// ---------------- setup kernels ----------------
__global__ void k_biasI(const float* __restrict__ ebih, const float* __restrict__ ebhh,
                        const float* __restrict__ dbih, const float* __restrict__ dbhh) {
    int n = blockIdx.x * blockDim.x + threadIdx.x;
    if (n < GDIM) {
        int j = n >> 2, g = n & 3;
        int r = g * 512 + j;
        g_bIenc[n] = ebih[r] + ebhh[r];
        g_bIdec[n] = dbih[r] + dbhh[r];
    }
}

__global__ void k_w16_enc(const float* __restrict__ Whh) {
    size_t idx = (size_t)blockIdx.x * blockDim.x + threadIdx.x;
    if (idx >= (size_t)GDIM * HDIM) return;
    int n = (int)(idx >> 9);
    int k = (int)(idx & 511);
    int j = n >> 2, g = n & 3;
    g_We16[idx] = __float2half(Whh[(size_t)(g * 512 + j) * 512 + k]);
}

__global__ void k_w16_dec(const float* __restrict__ dWih, const float* __restrict__ dWhh) {
    size_t idx = (size_t)blockIdx.x * blockDim.x + threadIdx.x;
    if (idx >= (size_t)GDIM * 1024) return;
    int n = (int)(idx >> 10);
    int k = (int)(idx & 1023);
    int j = n >> 2, g = n & 3;
    int row = g * 512 + j;
    float v = (k < 512) ? dWhh[(size_t)row * 512 + k]
                        : dWih[(size_t)row * (EDIM + HDIM) + EDIM + (k - 512)];
    g_Wd16[idx] = __float2half(v);
}

__global__ void k_w16_attn(const float* __restrict__ attnW) {
    size_t idx = (size_t)blockIdx.x * blockDim.x + threadIdx.x;
    if (idx >= (size_t)HDIM * HDIM) return;
    int n = (int)(idx >> 9);
    int k = (int)(idx & 511);
    g_Wh16[idx] = __float2half(attnW[(size_t)n * 1024 + k]);
    g_Wat16[idx] = __float2half(attnW[(size_t)n * 1024 + 512 + k]);
}

__global__ void k_w16_wih(const float* __restrict__ eWih, const float* __restrict__ dWih) {
    size_t idx = (size_t)blockIdx.x * blockDim.x + threadIdx.x;
    if (idx >= (size_t)GDIM * EDIM) return;
    int n = (int)(idx >> 8);
    int k = (int)(idx & 255);
    int j = n >> 2, g = n & 3;
    int row = g * 512 + j;
    g_WihE16[idx] = __float2half(eWih[(size_t)row * EDIM + k]);
    g_WihD16[idx] = __float2half(dWih[(size_t)row * (EDIM + HDIM) + k]);
}

__global__ void k_gather_enc(const float* __restrict__ emb, const int* __restrict__ src) {
    int m = blockIdx.x;
    int e = threadIdx.x;
    int s = m >> 6, b = m & 63;
    int tok = src[b * SLEN + s];
    g_encX16[(size_t)m * EDIM + e] = __float2half(emb[(size_t)tok * EDIM + e]);
}

__global__ void k_gather_dec(const float* __restrict__ emb, const int* __restrict__ trg) {
    int m = blockIdx.x;
    int e = threadIdx.x;
    int t = m >> 6, b = m & 63;
    int tok = trg[b * TLEN + t];
    g_decX16[(size_t)m * EDIM + e] = __float2half(emb[(size_t)tok * EDIM + e]);
}

__global__ void k_zero_out(float* __restrict__ out) {
    size_t idx = (size_t)blockIdx.x * blockDim.x + threadIdx.x;
    if (idx >= (size_t)BATCH * VCAB) return;
    size_t b = idx / VCAB, v = idx % VCAB;
    out[b * (size_t)TLEN * VCAB + v] = 0.0f;
}

__global__ void k_zero_state() {
    int i = blockIdx.x * blockDim.x + threadIdx.x;
    if (i < BATCH * HDIM) {
        g_eh16[0][i] = __float2half(0.0f);
        g_c[i] = 0.0f;
    }
}

__global__ void k_init_dec() {
    int i = blockIdx.x * blockDim.x + threadIdx.x;
    int b = i >> 9, j = i & 511;
    g_xh16[0][b * 1024 + j] = g_eh16[0][b * 512 + j];
}

__global__ void k_convB_h(const float* __restrict__ W) {
    size_t i4 = (size_t)blockIdx.x * blockDim.x + threadIdx.x;
    if (i4 * 4 >= (size_t)VCAB * KD) return;
    float4 v = *reinterpret_cast<const float4*>(W + i4 * 4);
    __half2* dst = reinterpret_cast<__half2*>(g_Bhf + i4 * 4);
    dst[0] = __floats2half2_rn(v.x, v.y);
    dst[1] = __floats2half2_rn(v.z, v.w);
}

// ============ shared fp16 GEMM tile machinery ============
template <int NCH>
__device__ __forceinline__ void load_AB16(uint32_t Ab, uint32_t Bb,
                                          const __half* __restrict__ Aglob, int apitchB,
                                          const __half* __restrict__ Bglob, int bpitchB,
                                          int n0, int tid) {
    for (int i = tid; i < 64 * 8 * NCH; i += 256) {
        int kc = i >> 9, rem = i & 511;
        int r = rem >> 3, s = rem & 7;
        uint32_t dst = Ab + kc * 8192 + (r << 7) + (((s ^ (r & 7)) << 4));
        const char* src = (const char*)Aglob + (size_t)r * apitchB + kc * 128 + (s << 4);
        cpa16(dst, src);
    }
    for (int i = tid; i < 32 * 8 * NCH; i += 256) {
        int kc = i >> 8, rem = i & 255;
        int r = rem >> 3, s = rem & 7;
        uint32_t dst = Bb + kc * 4096 + (r << 7) + (((s ^ (r & 7)) << 4));
        const char* src = (const char*)Bglob + (size_t)(n0 + r) * bpitchB + kc * 128 + (s << 4);
        cpa16(dst, src);
    }
    cpa_commit();
    cpa_wait<0>();
    __syncthreads();
}

template <int NCH>
__device__ __forceinline__ void mma_64x32(uint32_t Ab, uint32_t Bb, int lane, int wm, int wn,
                                          float acc[2][4]) {
    const int g = lane >> 3, lr = lane & 7;
    for (int kc = 0; kc < NCH; kc++) {
#pragma unroll
        for (int ks = 0; ks < 4; ks++) {
            uint32_t afr[4], bfr[4];
            {
                int row = wm * 16 + (g & 1) * 8 + lr;
                int kseg = ks * 2 + (g >> 1);
                uint32_t addr = Ab + kc * 8192 + (row << 7) + (((kseg ^ (row & 7)) << 4));
                LDMX4(afr, addr);
            }
            {
                int row = wn * 16 + (g >> 1) * 8 + lr;
                int kseg = ks * 2 + (g & 1);
                uint32_t addr = Bb + kc * 4096 + (row << 7) + (((kseg ^ (row & 7)) << 4));
                LDMX4(bfr, addr);
            }
            mma16816(acc[0], afr, bfr[0], bfr[1]);
            mma16816(acc[1], afr, bfr[2], bfr[3]);
        }
    }
}

// ---------------- fp16 projection GEMM (generalized): C = A @ B^T + bias ----------------
// sel 0: encoder xproj (K=256) | sel 1: decoder xproj (K=256) | sel 2: encWe (K=512, fp16 out)
__global__ void __launch_bounds__(256, 1) hgemm_proj(int sel, const float* __restrict__ bias_ext) {
    const __half* A;
    const __half* B;
    const float* biasI;
    float* C = nullptr;
    int Mlim, ldc, kch, kpitch;
    if (sel == 0) {
        A = g_encX16; B = g_WihE16; biasI = g_bIenc; C = g_xprojE;
        Mlim = SLEN * BATCH; ldc = GDIM; kch = 4; kpitch = EDIM * 2;
    } else if (sel == 1) {
        A = g_decX16; B = g_WihD16; biasI = g_bIdec; C = g_decxp;
        Mlim = TD * BATCH; ldc = GDIM; kch = 4; kpitch = EDIM * 2;
    } else {
        A = g_encout16; B = g_Wat16; biasI = bias_ext;
        Mlim = SLEN * BATCH; ldc = HDIM; kch = 8; kpitch = HDIM * 2;
    }

    extern __shared__ char smc[];
    const uint32_t sbase = smem_u32(smc);
    const int tid = threadIdx.x;
    const int wid = tid >> 5, lane = tid & 31;
    const int m0 = blockIdx.x * 128;
    const int n0 = blockIdx.y * 128;
    const int wm = wid >> 2, wn = wid & 3;

    const char* Ag = (const char*)A + (size_t)m0 * kpitch;
    const char* Bg = (const char*)B + (size_t)n0 * kpitch;

    float acc[4][4][4];
#pragma unroll
    for (int i = 0; i < 4; i++)
#pragma unroll
        for (int j = 0; j < 4; j++)
#pragma unroll
            for (int r = 0; r < 4; r++) acc[i][j][r] = 0.0f;

    auto load_chunk = [&](int kc, int slot) {
        uint32_t st = sbase + (uint32_t)slot * 32768;
#pragma unroll
        for (int i = 0; i < 8; i++) {
            int idx = tid + (i << 8);
            int isB = idx >> 10;
            int r = (idx & 1023) >> 3;
            int seg = idx & 7;
            uint32_t dst = st + (isB ? 16384u : 0u) + (uint32_t)(r << 7)
                         + (uint32_t)(((seg ^ (r & 7)) << 4));
            const char* src = (isB ? Bg : Ag) + (size_t)r * kpitch + (size_t)kc * 128 + (seg << 4);
            cpa16(dst, src);
        }
        cpa_commit();
    };

    const int g = lane >> 3, lr = lane & 7;
    auto compute = [&](int slot) {
        uint32_t Abase = sbase + (uint32_t)slot * 32768;
        uint32_t Bbase = Abase + 16384u;
#pragma unroll
        for (int ks = 0; ks < 4; ks++) {
            uint32_t afr[4][4];
#pragma unroll
            for (int mt = 0; mt < 4; mt++) {
                int row = wm * 64 + mt * 16 + (g & 1) * 8 + lr;
                int kseg = ks * 2 + (g >> 1);
                uint32_t addr = Abase + (uint32_t)(row << 7) + (uint32_t)(((kseg ^ (row & 7)) << 4));
                LDMX4(afr[mt], addr);
            }
            uint32_t bfr[2][4];
#pragma unroll
            for (int np = 0; np < 2; np++) {
                int row = wn * 32 + np * 16 + (g >> 1) * 8 + lr;
                int kseg = ks * 2 + (g & 1);
                uint32_t addr = Bbase + (uint32_t)(row << 7) + (uint32_t)(((kseg ^ (row & 7)) << 4));
                LDMX4(bfr[np], addr);
            }
#pragma unroll
            for (int mt = 0; mt < 4; mt++)
#pragma unroll
                for (int nt = 0; nt < 4; nt++) {
                    const uint32_t* bp = &bfr[nt >> 1][(nt & 1) * 2];
                    mma16816(acc[mt][nt], afr[mt], bp[0], bp[1]);
                }
        }
    };

    load_chunk(0, 0);
    load_chunk(1, 1);
    for (int i = 0; i < kch; i++) {
        if (i + 1 < kch) cpa_wait<1>(); else cpa_wait<0>();
        __syncthreads();
        if (i + 2 < kch) load_chunk(i + 2, (i + 2) % 3);
        compute(i % 3);
    }

    const int quad = lane >> 2, tq = lane & 3;
#pragma unroll
    for (int mt = 0; mt < 4; mt++) {
        int mr0 = m0 + wm * 64 + mt * 16 + quad;
#pragma unroll
        for (int half = 0; half < 2; half++) {
            int m = mr0 + half * 8;
            if (m >= Mlim) continue;
#pragma unroll
            for (int nt = 0; nt < 4; nt++) {
                int n = n0 + wn * 32 + nt * 8 + tq * 2;
                float v0 = acc[mt][nt][half * 2 + 0] + biasI[n];
                float v1 = acc[mt][nt][half * 2 + 1] + biasI[n + 1];
                if (sel == 2) {
                    __half* crow = g_encWe16 + (size_t)m * HDIM;
                    crow[n] = __float2half(v0);
                    crow[n + 1] = __float2half(v1);
                } else {
                    float* crow = C + (size_t)m * ldc;
                    crow[n] = v0;
                    crow[n + 1] = v1;
                }
            }
        }
    }
}

// ---------------- fused encoder step (fallback path): fp16 GEMM (64x32xK512) + LSTM ----------------
__global__ void __launch_bounds__(256, 1) enc_step16(int t) {
    extern __shared__ char sm[];
    const uint32_t Ab = smem_u32(sm);
    const uint32_t Bb = Ab + 65536;
    float* gsm = (float*)(sm + 65536 + 32768);   // [64][33]
    const int tid = threadIdx.x, bid = blockIdx.x;
    const int wid = tid >> 5, lane = tid & 31;
    const int wm = wid >> 1, wn = wid & 1;

    load_AB16<8>(Ab, Bb, g_eh16[t & 1], HDIM * 2, g_We16, HDIM * 2, bid * 32, tid);

    float acc[2][4] = {{0.f, 0.f, 0.f, 0.f}, {0.f, 0.f, 0.f, 0.f}};
    mma_64x32<8>(Ab, Bb, lane, wm, wn, acc);

    const int quad = lane >> 2, tq = lane & 3;
#pragma unroll
    for (int nt = 0; nt < 2; nt++) {
        int cb = wn * 16 + nt * 8 + tq * 2;
        int r0 = wm * 16 + quad;
        gsm[r0 * 33 + cb] = acc[nt][0];
        gsm[r0 * 33 + cb + 1] = acc[nt][1];
        gsm[(r0 + 8) * 33 + cb] = acc[nt][2];
        gsm[(r0 + 8) * 33 + cb + 1] = acc[nt][3];
    }
    __syncthreads();

    const int b = tid & 63, jl = tid >> 6;
#pragma unroll
    for (int q = 0; q < 2; q++) {
        int j2 = jl + q * 4;
        int jd = bid * 8 + j2;
        float4 gv = *reinterpret_cast<const float4*>(
            &g_xprojE[((size_t)t * 64 + b) * GDIM + (size_t)jd * 4]);
        float gi = gsm[b * 33 + j2 * 4 + 0] + gv.x;
        float gf = gsm[b * 33 + j2 * 4 + 1] + gv.y;
        float gg = gsm[b * 33 + j2 * 4 + 2] + gv.z;
        float go = gsm[b * 33 + j2 * 4 + 3] + gv.w;
        int ci = b * 512 + jd;
        float cc = sigf(gf) * g_c[ci] + sigf(gi) * tanhf(gg);
        float hh = sigf(go) * tanhf(cc);
        g_c[ci] = cc;
        __half h16 = __float2half(hh);
        g_eh16[(t + 1) & 1][ci] = h16;
        g_encout16[((size_t)b * SLEN + t) * 512 + jd] = h16;
    }
}

// ---------------- clustered encoder: ALL 128 steps in ONE launch ----------------
// grid = 16 blocks = ONE cluster. Block bid owns interleaved n-cols [bid*128, +128)
// = j-dims [bid*32, +32). B slice (128 rows x 512 k) cached in smem once.
// Per step: cp.async A (h, 64KB, .cg = L2 path) -> mma 64x128x512 -> LSTM (c in regs)
// -> store h fp16 -> threadfence + barrier.cluster (release/acquire).
__global__ void __launch_bounds__(256, 1) enc_cluster() {
    extern __shared__ char sm[];
    const uint32_t Ab = smem_u32(sm);            // 64KB: A, 8 chunks x 64 rows x 128B
    const uint32_t Bb = Ab + 65536;              // 128KB: B, 8 chunks x 128 rows x 128B
    float* gsm = (float*)(sm + 65536 + 131072);  // [64][132]
    const int tid = threadIdx.x, bid = blockIdx.x;
    const int wid = tid >> 5, lane = tid & 31;
    const int wm = wid & 3, wn = wid >> 2;       // warp tile 16m x 64n
    const int g = lane >> 3, lr = lane & 7;
    const int n0 = bid * 128;

    // load B slice once (rows n0..n0+127, pitch 1024B)
    for (int i = tid; i < 128 * 8 * 8; i += 256) {
        int kc = i >> 10, rem = i & 1023;
        int r = rem >> 3, s = rem & 7;
        uint32_t dst = Bb + kc * 16384 + (r << 7) + (((s ^ (r & 7)) << 4));
        const char* src = (const char*)g_We16 + (size_t)(n0 + r) * (HDIM * 2) + kc * 128 + (s << 4);
        cpa16(dst, src);
    }
    cpa_commit();
    cpa_wait<0>();
    __syncthreads();

    const int b = tid & 63, jg = tid >> 6;
    float c_reg[8];
#pragma unroll
    for (int q = 0; q < 8; q++) c_reg[q] = 0.0f;

    for (int t = 0; t < SLEN; t++) {
        // load A = h(t) (64 rows x 1KB)
        const char* hsrc = (const char*)g_eh16[t & 1];
        for (int i = tid; i < 64 * 8 * 8; i += 256) {
            int kc = i >> 9, rem = i & 511;
            int r = rem >> 3, s = rem & 7;
            uint32_t dst = Ab + kc * 8192 + (r << 7) + (((s ^ (r & 7)) << 4));
            cpa16(dst, hsrc + (size_t)r * 1024 + kc * 128 + (s << 4));
        }
        cpa_commit();
        cpa_wait<0>();
        __syncthreads();

        float acc[8][4];
#pragma unroll
        for (int i = 0; i < 8; i++)
#pragma unroll
            for (int r = 0; r < 4; r++) acc[i][r] = 0.0f;

        for (int kc = 0; kc < 8; kc++) {
#pragma unroll
            for (int ks = 0; ks < 4; ks++) {
                uint32_t afr[4];
                {
                    int row = wm * 16 + (g & 1) * 8 + lr;
                    int kseg = ks * 2 + (g >> 1);
                    uint32_t addr = Ab + kc * 8192 + (row << 7) + (((kseg ^ (row & 7)) << 4));
                    LDMX4(afr, addr);
                }
#pragma unroll
                for (int nf = 0; nf < 4; nf++) {
                    uint32_t bfr[4];
                    int row = wn * 64 + nf * 16 + (g >> 1) * 8 + lr;
                    int kseg = ks * 2 + (g & 1);
                    uint32_t addr = Bb + kc * 16384 + (row << 7) + (((kseg ^ (row & 7)) << 4));
                    LDMX4(bfr, addr);
                    mma16816(acc[nf * 2], afr, bfr[0], bfr[1]);
                    mma16816(acc[nf * 2 + 1], afr, bfr[2], bfr[3]);
                }
            }
        }

        const int quad = lane >> 2, tq = lane & 3;
#pragma unroll
        for (int j = 0; j < 8; j++) {
            int cb = wn * 64 + j * 8 + tq * 2;
            int r0 = wm * 16 + quad;
            gsm[r0 * 132 + cb] = acc[j][0];
            gsm[r0 * 132 + cb + 1] = acc[j][1];
            gsm[(r0 + 8) * 132 + cb] = acc[j][2];
            gsm[(r0 + 8) * 132 + cb + 1] = acc[j][3];
        }
        __syncthreads();

        // LSTM for this block's 32 j-dims (8 per thread); c stays in registers
#pragma unroll
        for (int q = 0; q < 8; q++) {
            int j2 = jg * 8 + q;
            int jd = bid * 32 + j2;
            float4 gv = *reinterpret_cast<const float4*>(
                &g_xprojE[((size_t)t * 64 + b) * GDIM + (size_t)jd * 4]);
            float gi = gsm[b * 132 + j2 * 4 + 0] + gv.x;
            float gf = gsm[b * 132 + j2 * 4 + 1] + gv.y;
            float gg = gsm[b * 132 + j2 * 4 + 2] + gv.z;
            float go = gsm[b * 132 + j2 * 4 + 3] + gv.w;
            float cc = sigf(gf) * c_reg[q] + sigf(gi) * tanhf(gg);
            float hh = sigf(go) * tanhf(cc);
            c_reg[q] = cc;
            __half h16 = __float2half(hh);
            g_eh16[(t + 1) & 1][b * 512 + jd] = h16;
            g_encout16[((size_t)b * SLEN + t) * 512 + jd] = h16;
        }

        __threadfence();     // make h writes gpu-visible before barrier release
        cluster_bar();       // release/acquire across the 16-block cluster
    }

    // persist final c for the decoder
#pragma unroll
    for (int q = 0; q < 8; q++) {
        int jd = bid * 32 + jg * 8 + q;
        g_c[b * 512 + jd] = c_reg[q];
    }
}

// ---------------- decoder hWh: fp16 GEMM (64x32xK512), direct fp32 store ----------------
__global__ void __launch_bounds__(256, 1) dec_hwh16(int t) {
    extern __shared__ char sm[];
    const uint32_t Ab = smem_u32(sm);
    const uint32_t Bb = Ab + 65536;
    const int tid = threadIdx.x, bid = blockIdx.x;
    const int wid = tid >> 5, lane = tid & 31;
    const int wm = wid >> 1, wn = wid & 1;

    load_AB16<8>(Ab, Bb, g_xh16[t & 1], 1024 * 2, g_Wh16, HDIM * 2, bid * 32, tid);

    float acc[2][4] = {{0.f, 0.f, 0.f, 0.f}, {0.f, 0.f, 0.f, 0.f}};
    mma_64x32<8>(Ab, Bb, lane, wm, wn, acc);

    const int quad = lane >> 2, tq = lane & 3;
#pragma unroll
    for (int nt = 0; nt < 2; nt++) {
        int n = bid * 32 + wn * 16 + nt * 8 + tq * 2;
        int r0 = wm * 16 + quad;
        g_hwh[r0 * 512 + n] = acc[nt][0];
        g_hwh[r0 * 512 + n + 1] = acc[nt][1];
        g_hwh[(r0 + 8) * 512 + n] = acc[nt][2];
        g_hwh[(r0 + 8) * 512 + n + 1] = acc[nt][3];
    }
}

// ---------------- decoder attention (fp16 encWe / encout inputs) ----------------
__global__ void __launch_bounds__(256, 1) k_attn(const float* __restrict__ vw, int t) {
    __shared__ float hwhs[512];
    __shared__ float vws[512];
    __shared__ float sc[128];
    __shared__ float red[128];
    const int bb = blockIdx.x;
    const int tid = threadIdx.x;
    const int cur = t & 1;

    for (int i = tid; i < 512; i += 256) {
        hwhs[i] = g_hwh[bb * 512 + i];
        vws[i] = vw[i];
    }
    __syncthreads();
    int warp = tid >> 5, lane = tid & 31;
    for (int s = warp; s < SLEN; s += 8) {
        const __half2* we2 = reinterpret_cast<const __half2*>(
            &g_encWe16[((size_t)bb * SLEN + s) * 512]);
        float a = 0.0f;
        for (int j2 = lane; j2 < 256; j2 += 32) {
            float2 wf = __half22float2(we2[j2]);
            int j = j2 * 2;
            a += tanhf(hwhs[j] + wf.x) * vws[j];
            a += tanhf(hwhs[j + 1] + wf.y) * vws[j + 1];
        }
#pragma unroll
        for (int o = 16; o > 0; o >>= 1) a += __shfl_xor_sync(0xffffffffu, a, o);
        if (lane == 0) sc[s] = a;
    }
    __syncthreads();
    if (tid < SLEN) red[tid] = sc[tid];
    __syncthreads();
    for (int o = 64; o > 0; o >>= 1) {
        if (tid < o) red[tid] = fmaxf(red[tid], red[tid + o]);
        __syncthreads();
    }
    float mx = red[0];
    __syncthreads();
    float e = 0.0f;
    if (tid < SLEN) { e = expf(sc[tid] - mx); red[tid] = e; }
    __syncthreads();
    for (int o = 64; o > 0; o >>= 1) {
        if (tid < o) red[tid] += red[tid + o];
        __syncthreads();
    }
    float inv = 1.0f / red[0];
    __syncthreads();
    if (tid < SLEN) sc[tid] = e * inv;
    __syncthreads();

    float c0 = 0.0f, c1 = 0.0f;
    const __half* eo = &g_encout16[(size_t)bb * SLEN * 512];
    for (int s = 0; s < SLEN; s++) {
        float w = sc[s];
        c0 += w * __half2float(eo[s * 512 + tid]);
        c1 += w * __half2float(eo[s * 512 + tid + 256]);
    }
    __half h0 = __float2half(c0), h1 = __float2half(c1);
    g_xh16[cur][bb * 1024 + 512 + tid] = h0;
    g_xh16[cur][bb * 1024 + 512 + tid + 256] = h1;
    size_t ma = ((size_t)t * 64 + bb) * 1024;
    g_Ahf[ma + 512 + tid] = h0;
    g_Ahf[ma + 512 + tid + 256] = h1;
}

// ---------------- fused decoder gates: fp16 GEMM (64x32xK1024) + LSTM ----------------
__global__ void __launch_bounds__(256, 1) dec_gates16(int t) {
    extern __shared__ char sm[];
    const uint32_t Ab = smem_u32(sm);
    const uint32_t Bb = Ab + 131072;
    float* gsm = (float*)(sm + 131072 + 65536);   // [64][33]
    const int tid = threadIdx.x, bid = blockIdx.x;
    const int wid = tid >> 5, lane = tid & 31;
    const int wm = wid >> 1, wn = wid & 1;

    load_AB16<16>(Ab, Bb, g_xh16[t & 1], 1024 * 2, g_Wd16, 1024 * 2, bid * 32, tid);

    float acc[2][4] = {{0.f, 0.f, 0.f, 0.f}, {0.f, 0.f, 0.f, 0.f}};
    mma_64x32<16>(Ab, Bb, lane, wm, wn, acc);

    const int quad = lane >> 2, tq = lane & 3;
#pragma unroll
    for (int nt = 0; nt < 2; nt++) {
        int cb = wn * 16 + nt * 8 + tq * 2;
        int r0 = wm * 16 + quad;
        gsm[r0 * 33 + cb] = acc[nt][0];
        gsm[r0 * 33 + cb + 1] = acc[nt][1];
        gsm[(r0 + 8) * 33 + cb] = acc[nt][2];
        gsm[(r0 + 8) * 33 + cb + 1] = acc[nt][3];
    }
    __syncthreads();

    const int b = tid & 63, jl = tid >> 6;
#pragma unroll
    for (int q = 0; q < 2; q++) {
        int j2 = jl + q * 4;
        int jd = bid * 8 + j2;
        float4 gv = *reinterpret_cast<const float4*>(
            &g_decxp[((size_t)t * 64 + b) * GDIM + (size_t)jd * 4]);
        float gi = gsm[b * 33 + j2 * 4 + 0] + gv.x;
        float gf = gsm[b * 33 + j2 * 4 + 1] + gv.y;
        float gg = gsm[b * 33 + j2 * 4 + 2] + gv.z;
        float go = gsm[b * 33 + j2 * 4 + 3] + gv.w;
        int ci = b * 512 + jd;
        float cc = sigf(gf) * g_c[ci] + sigf(gi) * tanhf(gg);
        float hh = sigf(go) * tanhf(cc);
        g_c[ci] = cc;
        __half h16 = __float2half(hh);
        g_xh16[(t + 1) & 1][b * 1024 + jd] = h16;
        g_Ahf[((size_t)t * 64 + b) * 1024 + jd] = h16;
    }
}

// ---------------- fp16 tensor-core fc GEMM: tile 128M x 256N, K=1024 ----------------
__global__ void __launch_bounds__(256, 1) hgemm_fc(const float* __restrict__ fc_b,
                                                   float* __restrict__ out) {
    extern __shared__ char smc[];
    const uint32_t sbase = smem_u32(smc);
    const int tid = threadIdx.x;
    const int wid = tid >> 5, lane = tid & 31;
    const int m0 = blockIdx.x * 128;
    const int n0 = blockIdx.y * 256;
    const int wm = wid >> 2;
    const int wn = wid & 3;

    const char* Ag = (const char*)g_Ahf + (size_t)m0 * (KD * 2);
    const char* Bg = (const char*)g_Bhf + (size_t)n0 * (KD * 2);

    float acc[4][8][4];
#pragma unroll
    for (int i = 0; i < 4; i++)
#pragma unroll
        for (int j = 0; j < 8; j++)
#pragma unroll
            for (int r = 0; r < 4; r++) acc[i][j][r] = 0.0f;

    auto load_chunk = [&](int kc, int slot) {
        uint32_t st = sbase + (uint32_t)slot * STGB;
#pragma unroll
        for (int i = 0; i < 12; i++) {
            int idx = tid + (i << 8);
            int isB = idx >= 1024;
            int r = (isB ? (idx - 1024) : idx) >> 3;
            int seg = idx & 7;
            uint32_t dst = st + (isB ? 16384u : 0u) + (uint32_t)(r << 7)
                         + (uint32_t)(((seg ^ (r & 7)) << 4));
            const char* src = (isB ? Bg : Ag) + (size_t)r * (KD * 2) + (size_t)kc * 128 + (seg << 4);
            cpa16(dst, src);
        }
        cpa_commit();
    };

    const int g = lane >> 3, lr = lane & 7;

    auto compute = [&](int slot) {
        uint32_t Abase = sbase + (uint32_t)slot * STGB;
        uint32_t Bbase = Abase + 16384u;
#pragma unroll
        for (int ks = 0; ks < 4; ks++) {
            uint32_t afr[4][4];
#pragma unroll
            for (int mt = 0; mt < 4; mt++) {
                int row = wm * 64 + mt * 16 + (g & 1) * 8 + lr;
                int kseg = ks * 2 + (g >> 1);
                uint32_t addr = Abase + (uint32_t)(row << 7) + (uint32_t)(((kseg ^ (row & 7)) << 4));
                LDMX4(afr[mt], addr);
            }
            uint32_t bfr[4][4];
#pragma unroll
            for (int np = 0; np < 4; np++) {
                int row = wn * 64 + np * 16 + (g >> 1) * 8 + lr;
                int kseg = ks * 2 + (g & 1);
                uint32_t addr = Bbase + (uint32_t)(row << 7) + (uint32_t)(((kseg ^ (row & 7)) << 4));
                LDMX4(bfr[np], addr);
            }
#pragma unroll
            for (int mt = 0; mt < 4; mt++)
#pragma unroll
                for (int nt = 0; nt < 8; nt++) {
                    const uint32_t* bp = &bfr[nt >> 1][(nt & 1) * 2];
                    mma16816(acc[mt][nt], afr[mt], bp[0], bp[1]);
                }
        }
    };

    load_chunk(0, 0);
    load_chunk(1, 1);
    for (int i = 0; i < NCHK; i++) {
        if (i + 1 < NCHK) cpa_wait<1>(); else cpa_wait<0>();
        __syncthreads();
        if (i + 2 < NCHK) load_chunk(i + 2, (i + 2) % 3);
        compute(i % 3);
    }

    const int quad = lane >> 2, tq = lane & 3;
#pragma unroll
    for (int mt = 0; mt < 4; mt++) {
        int mr0 = m0 + wm * 64 + mt * 16 + quad;
#pragma unroll
        for (int half = 0; half < 2; half++) {
            int m = mr0 + half * 8;
            if (m >= TD * BATCH) continue;
            int bb = m & 63, tt = m >> 6;
            float* orow = out + ((size_t)bb * TLEN + (tt + 1)) * VCAB;
#pragma unroll
            for (int nt = 0; nt < 8; nt++) {
                int n = n0 + wn * 64 + nt * 8 + tq * 2;
                float v0 = acc[mt][nt][half * 2 + 0];
                float v1 = acc[mt][nt][half * 2 + 1];
                if (n < VCAB)     orow[n]     = v0 + fc_b[n];
                if (n + 1 < VCAB) orow[n + 1] = v1 + fc_b[n + 1];
            }
        }
    }
}

// ---------------- host driver ----------------
extern "C" void kernel_launch(void* const* d_in, const int* in_sizes, int n_in,
                              void* d_out, int out_size) {
    const int*   src     = (const int*)  d_in[0];
    const int*   trg     = (const int*)  d_in[1];
    const float* enc_emb = (const float*)d_in[2];
    const float* enc_Wih = (const float*)d_in[3];
    const float* enc_Whh = (const float*)d_in[4];
    const float* enc_bih = (const float*)d_in[5];
    const float* enc_bhh = (const float*)d_in[6];
    const float* dec_emb = (const float*)d_in[7];
    const float* dec_Wih = (const float*)d_in[8];
    const float* dec_Whh = (const float*)d_in[9];
    const float* dec_bih = (const float*)d_in[10];
    const float* dec_bhh = (const float*)d_in[11];
    const float* attn_W  = (const float*)d_in[12];
    const float* attn_b  = (const float*)d_in[13];
    const float* v_w     = (const float*)d_in[14];
    const float* fc_W    = (const float*)d_in[15];
    const float* fc_b    = (const float*)d_in[16];
    float* out = (float*)d_out;
    (void)in_sizes; (void)n_in; (void)out_size;

    const int ENC_SMEM = 65536 + 32768 + 64 * 33 * 4;        // 106752 (fallback)
    const int ENCC_SMEM = 65536 + 131072 + 64 * 132 * 4;     // 230400 (cluster)
    const int HWH_SMEM = 65536 + 32768;                      // 98304
    const int DEC_SMEM = 131072 + 65536 + 64 * 33 * 4;       // 205056
    const int PROJ_SMEM = 3 * 32768;                         // 98304
    cudaFuncSetAttribute(hgemm_fc, cudaFuncAttributeMaxDynamicSharedMemorySize, 3 * STGB);
    cudaFuncSetAttribute(hgemm_proj, cudaFuncAttributeMaxDynamicSharedMemorySize, PROJ_SMEM);
    cudaFuncSetAttribute(enc_step16, cudaFuncAttributeMaxDynamicSharedMemorySize, ENC_SMEM);
    cudaFuncSetAttribute(dec_hwh16, cudaFuncAttributeMaxDynamicSharedMemorySize, HWH_SMEM);
    cudaFuncSetAttribute(dec_gates16, cudaFuncAttributeMaxDynamicSharedMemorySize, DEC_SMEM);

    // cluster-path feasibility (deterministic host queries; no stream ops)
    cudaError_t e1 = cudaFuncSetAttribute(enc_cluster,
        cudaFuncAttributeMaxDynamicSharedMemorySize, ENCC_SMEM);
    cudaError_t e2 = cudaFuncSetAttribute(enc_cluster,
        cudaFuncAttributeNonPortableClusterSizeAllowed, 1);
    cudaLaunchConfig_t ccfg = {};
    ccfg.gridDim = {16, 1, 1};
    ccfg.blockDim = {256, 1, 1};
    ccfg.dynamicSmemBytes = ENCC_SMEM;
    cudaLaunchAttribute cattr[1];
    cattr[0].id = cudaLaunchAttributeClusterDimension;
    cattr[0].val.clusterDim = {16, 1, 1};
    ccfg.attrs = cattr;
    ccfg.numAttrs = 1;
    int maxClu = 0;
    cudaError_t e3 = (e1 == cudaSuccess && e2 == cudaSuccess)
        ? cudaOccupancyMaxPotentialClusterSize(&maxClu, enc_cluster, &ccfg)
        : cudaErrorInvalidValue;
    const bool useCluster = (e3 == cudaSuccess && maxClu >= 16);

    // setup
    k_biasI<<<8, 256>>>(enc_bih, enc_bhh, dec_bih, dec_bhh);
    k_w16_enc<<<(int)(((size_t)GDIM * HDIM + 255) / 256), 256>>>(enc_Whh);
    k_w16_dec<<<(int)(((size_t)GDIM * 1024 + 255) / 256), 256>>>(dec_Wih, dec_Whh);
    k_w16_attn<<<(int)(((size_t)HDIM * HDIM + 255) / 256), 256>>>(attn_W);
    k_w16_wih<<<(int)(((size_t)GDIM * EDIM + 255) / 256), 256>>>(enc_Wih, dec_Wih);
    k_gather_enc<<<SLEN * BATCH, EDIM>>>(enc_emb, src);
    k_gather_dec<<<TD * BATCH, EDIM>>>(dec_emb, trg);
    k_zero_out<<<(int)(((size_t)BATCH * VCAB + 255) / 256), 256>>>(out);
    k_zero_state<<<(BATCH * HDIM + 255) / 256, 256>>>();
    k_convB_h<<<(int)(((size_t)VCAB * KD / 4 + 255) / 256), 256>>>(fc_W);

    // fp16 input projections (interleaved output + bias)
    hgemm_proj<<<dim3((SLEN * BATCH) / 128, GDIM / 128), 256, PROJ_SMEM>>>(0, nullptr);
    hgemm_proj<<<dim3(MPAD / 128, GDIM / 128), 256, PROJ_SMEM>>>(1, nullptr);

    // encoder recurrence: clustered single launch, or per-step fallback
    if (useCluster) {
        cudaLaunchKernelEx(&ccfg, enc_cluster);
    } else {
        for (int t = 0; t < SLEN; t++)
            enc_step16<<<64, 256, ENC_SMEM>>>(t);
    }

    // encWe = enc_out @ attn_W[:, H:]^T + attn_b (fp16 mma, fp16 output)
    hgemm_proj<<<dim3((SLEN * BATCH) / 128, HDIM / 128), 256, PROJ_SMEM>>>(2, attn_b);

    k_init_dec<<<128, 256>>>();

    // decoder: THREE kernels per step (proven R12 structure)
    for (int t = 0; t < TD; t++) {
        dec_hwh16<<<16, 256, HWH_SMEM>>>(t);
        k_attn<<<64, 256>>>(v_w, t);
        dec_gates16<<<64, 256, DEC_SMEM>>>(t);
    }

    // tensor-core fc GEMM (128 x 256 tiles)
    hgemm_fc<<<dim3(MPAD / 128, NPAD / 256), 256, 3 * STGB>>>(fc_b, out);
}

// round 16
// speedup vs baseline: 1.2244x; 1.0795x over previous
#include <cuda_runtime.h>
#include <cuda_fp16.h>
#include <math.h>
#include <stdint.h>

#define VCAB 50257
#define EDIM 256
#define HDIM 512
#define BATCH 64
#define SLEN 128
#define TLEN 64
#define TD 63            // decoder steps (T-1)
#define GDIM 2048        // 4*H

// fc GEMM dims (fp16 mma.sync path)
#define KD 1024
#define MPAD 4096
#define NPAD 50432       // 197 * 256
#define NCHK 16          // KD / 64
#define STGB 49152       // fc stage bytes: A 16KB + B 32KB

// ---------------- scratch (static device allocations; no cudaMalloc) ----------------
__device__ __align__(16) float g_bIenc[GDIM];
__device__ __align__(16) float g_bIdec[GDIM];
__device__ __align__(16) float g_xprojE[(size_t)SLEN * BATCH * GDIM];  // INTERLEAVED [m][j*4+g]
__device__ __align__(16) float g_decxp[(size_t)MPAD * GDIM];           // INTERLEAVED
__device__ __align__(16) float g_c[BATCH * HDIM];
__device__ __align__(16) float g_hwh[BATCH * HDIM];
// fp16 embeddings / states
__device__ __align__(16) __half g_encX16[(size_t)SLEN * BATCH * EDIM];
__device__ __align__(16) __half g_decX16[(size_t)MPAD * EDIM];
__device__ __align__(16) __half g_encout16[(size_t)BATCH * SLEN * HDIM];
__device__ __align__(16) __half g_encWe16[(size_t)BATCH * SLEN * HDIM];
__device__ __align__(16) __half g_eh16[2][BATCH * HDIM];
__device__ __align__(16) __half g_xh16[2][BATCH * 1024];
// fp16 gate-interleaved weights
__device__ __align__(16) __half g_We16[(size_t)GDIM * HDIM];
__device__ __align__(16) __half g_Wd16[(size_t)GDIM * 1024];
__device__ __align__(16) __half g_WihE16[(size_t)GDIM * EDIM];
__device__ __align__(16) __half g_WihD16[(size_t)GDIM * EDIM];
// attention weights [n][k]
__device__ __align__(16) __half g_Wh16[(size_t)HDIM * HDIM];
__device__ __align__(16) __half g_Wat16[(size_t)HDIM * HDIM];
// fp16 operands for the tensor-core fc GEMM (pad rows stay zero: never written)
__device__ __align__(16) __half g_Ahf[(size_t)MPAD * KD];
__device__ __align__(16) __half g_Bhf[(size_t)NPAD * KD];

__device__ __forceinline__ float sigf(float x) { return 1.0f / (1.0f + expf(-x)); }

// ---------------- PTX helpers (compute_103-safe) ----------------
__device__ __forceinline__ uint32_t smem_u32(const void* p) {
    uint32_t a;
    asm("{ .reg .u64 t; cvta.to.shared.u64 t, %1; cvt.u32.u64 %0, t; }" : "=r"(a) : "l"(p));
    return a;
}
__device__ __forceinline__ void cpa16(uint32_t dst, const void* src) {
    asm volatile("cp.async.cg.shared.global [%0], [%1], 16;" :: "r"(dst), "l"(src) : "memory");
}
__device__ __forceinline__ void cpa_commit() { asm volatile("cp.async.commit_group;" ::: "memory"); }
template <int N> __device__ __forceinline__ void cpa_wait() {
    asm volatile("cp.async.wait_group %0;" :: "n"(N) : "memory");
}
#define LDMX4(r, addr) \
    asm volatile("ldmatrix.sync.aligned.m8n8.x4.shared.b16 {%0,%1,%2,%3}, [%4];" \
        : "=r"((r)[0]), "=r"((r)[1]), "=r"((r)[2]), "=r"((r)[3]) : "r"(addr))
__device__ __forceinline__ void mma16816(float* c, const uint32_t* a, uint32_t b0, uint32_t b1) {
    asm volatile("mma.sync.aligned.m16n8k16.row.col.f32.f16.f16.f32 "
        "{%0,%1,%2,%3}, {%4,%5,%6,%7}, {%8,%9}, {%0,%1,%2,%3};"
        : "+f"(c[0]), "+f"(c[1]), "+f"(c[2]), "+f"(c[3])
        : "r"(a[0]), "r"(a[1]), "r"(a[2]), "r"(a[3]), "r"(b0), "r"(b1));
}

// ---------------- setup kernels ----------------
__global__ void k_biasI(const float* __restrict__ ebih, const float* __restrict__ ebhh,
                        const float* __restrict__ dbih, const float* __restrict__ dbhh) {
    int n = blockIdx.x * blockDim.x + threadIdx.x;
    if (n < GDIM) {
        int j = n >> 2, g = n & 3;
        int r = g * 512 + j;
        g_bIenc[n] = ebih[r] + ebhh[r];
        g_bIdec[n] = dbih[r] + dbhh[r];
    }
}

__global__ void k_w16_enc(const float* __restrict__ Whh) {
    size_t idx = (size_t)blockIdx.x * blockDim.x + threadIdx.x;
    if (idx >= (size_t)GDIM * HDIM) return;
    int n = (int)(idx >> 9);
    int k = (int)(idx & 511);
    int j = n >> 2, g = n & 3;
    g_We16[idx] = __float2half(Whh[(size_t)(g * 512 + j) * 512 + k]);
}

__global__ void k_w16_dec(const float* __restrict__ dWih, const float* __restrict__ dWhh) {
    size_t idx = (size_t)blockIdx.x * blockDim.x + threadIdx.x;
    if (idx >= (size_t)GDIM * 1024) return;
    int n = (int)(idx >> 10);
    int k = (int)(idx & 1023);
    int j = n >> 2, g = n & 3;
    int row = g * 512 + j;
    float v = (k < 512) ? dWhh[(size_t)row * 512 + k]
                        : dWih[(size_t)row * (EDIM + HDIM) + EDIM + (k - 512)];
    g_Wd16[idx] = __float2half(v);
}

__global__ void k_w16_attn(const float* __restrict__ attnW) {
    size_t idx = (size_t)blockIdx.x * blockDim.x + threadIdx.x;
    if (idx >= (size_t)HDIM * HDIM) return;
    int n = (int)(idx >> 9);
    int k = (int)(idx & 511);
    g_Wh16[idx] = __float2half(attnW[(size_t)n * 1024 + k]);
    g_Wat16[idx] = __float2half(attnW[(size_t)n * 1024 + 512 + k]);
}

__global__ void k_w16_wih(const float* __restrict__ eWih, const float* __restrict__ dWih) {
    size_t idx = (size_t)blockIdx.x * blockDim.x + threadIdx.x;
    if (idx >= (size_t)GDIM * EDIM) return;
    int n = (int)(idx >> 8);
    int k = (int)(idx & 255);
    int j = n >> 2, g = n & 3;
    int row = g * 512 + j;
    g_WihE16[idx] = __float2half(eWih[(size_t)row * EDIM + k]);
    g_WihD16[idx] = __float2half(dWih[(size_t)row * (EDIM + HDIM) + k]);
}

__global__ void k_gather_enc(const float* __restrict__ emb, const int* __restrict__ src) {
    int m = blockIdx.x;
    int e = threadIdx.x;
    int s = m >> 6, b = m & 63;
    int tok = src[b * SLEN + s];
    g_encX16[(size_t)m * EDIM + e] = __float2half(emb[(size_t)tok * EDIM + e]);
}

__global__ void k_gather_dec(const float* __restrict__ emb, const int* __restrict__ trg) {
    int m = blockIdx.x;
    int e = threadIdx.x;
    int t = m >> 6, b = m & 63;
    int tok = trg[b * TLEN + t];
    g_decX16[(size_t)m * EDIM + e] = __float2half(emb[(size_t)tok * EDIM + e]);
}

__global__ void k_zero_out(float* __restrict__ out) {
    size_t idx = (size_t)blockIdx.x * blockDim.x + threadIdx.x;
    if (idx >= (size_t)BATCH * VCAB) return;
    size_t b = idx / VCAB, v = idx % VCAB;
    out[b * (size_t)TLEN * VCAB + v] = 0.0f;
}

__global__ void k_zero_state() {
    int i = blockIdx.x * blockDim.x + threadIdx.x;
    if (i < BATCH * HDIM) {
        g_eh16[0][i] = __float2half(0.0f);
        g_c[i] = 0.0f;
    }
}

__global__ void k_init_dec() {
    int i = blockIdx.x * blockDim.x + threadIdx.x;
    int b = i >> 9, j = i & 511;
    g_xh16[0][b * 1024 + j] = g_eh16[0][b * 512 + j];
}

__global__ void k_convB_h(const float* __restrict__ W) {
    size_t i4 = (size_t)blockIdx.x * blockDim.x + threadIdx.x;
    if (i4 * 4 >= (size_t)VCAB * KD) return;
    float4 v = *reinterpret_cast<const float4*>(W + i4 * 4);
    __half2* dst = reinterpret_cast<__half2*>(g_Bhf + i4 * 4);
    dst[0] = __floats2half2_rn(v.x, v.y);
    dst[1] = __floats2half2_rn(v.z, v.w);
}

// ============ shared fp16 GEMM tile machinery ============
template <int NCH>
__device__ __forceinline__ void load_AB16(uint32_t Ab, uint32_t Bb,
                                          const __half* __restrict__ Aglob, int apitchB,
                                          const __half* __restrict__ Bglob, int bpitchB,
                                          int n0, int tid) {
    for (int i = tid; i < 64 * 8 * NCH; i += 256) {
        int kc = i >> 9, rem = i & 511;
        int r = rem >> 3, s = rem & 7;
        uint32_t dst = Ab + kc * 8192 + (r << 7) + (((s ^ (r & 7)) << 4));
        const char* src = (const char*)Aglob + (size_t)r * apitchB + kc * 128 + (s << 4);
        cpa16(dst, src);
    }
    for (int i = tid; i < 32 * 8 * NCH; i += 256) {
        int kc = i >> 8, rem = i & 255;
        int r = rem >> 3, s = rem & 7;
        uint32_t dst = Bb + kc * 4096 + (r << 7) + (((s ^ (r & 7)) << 4));
        const char* src = (const char*)Bglob + (size_t)(n0 + r) * bpitchB + kc * 128 + (s << 4);
        cpa16(dst, src);
    }
    cpa_commit();
    cpa_wait<0>();
    __syncthreads();
}

template <int NCH>
__device__ __forceinline__ void mma_64x32(uint32_t Ab, uint32_t Bb, int lane, int wm, int wn,
                                          float acc[2][4]) {
    const int g = lane >> 3, lr = lane & 7;
    for (int kc = 0; kc < NCH; kc++) {
#pragma unroll
        for (int ks = 0; ks < 4; ks++) {
            uint32_t afr[4], bfr[4];
            {
                int row = wm * 16 + (g & 1) * 8 + lr;
                int kseg = ks * 2 + (g >> 1);
                uint32_t addr = Ab + kc * 8192 + (row << 7) + (((kseg ^ (row & 7)) << 4));
                LDMX4(afr, addr);
            }
            {
                int row = wn * 16 + (g >> 1) * 8 + lr;
                int kseg = ks * 2 + (g & 1);
                uint32_t addr = Bb + kc * 4096 + (row << 7) + (((kseg ^ (row & 7)) << 4));
                LDMX4(bfr, addr);
            }
            mma16816(acc[0], afr, bfr[0], bfr[1]);
            mma16816(acc[1], afr, bfr[2], bfr[3]);
        }
    }
}

// ---------------- fp16 projection GEMM (generalized): C = A @ B^T + bias ----------------
// sel 0: encoder xproj (K=256) | sel 1: decoder xproj (K=256) | sel 2: encWe (K=512, fp16 out)
__global__ void __launch_bounds__(256, 1) hgemm_proj(int sel, const float* __restrict__ bias_ext) {
    const __half* A;
    const __half* B;
    const float* biasI;
    float* C = nullptr;
    int Mlim, ldc, kch, kpitch;
    if (sel == 0) {
        A = g_encX16; B = g_WihE16; biasI = g_bIenc; C = g_xprojE;
        Mlim = SLEN * BATCH; ldc = GDIM; kch = 4; kpitch = EDIM * 2;
    } else if (sel == 1) {
        A = g_decX16; B = g_WihD16; biasI = g_bIdec; C = g_decxp;
        Mlim = TD * BATCH; ldc = GDIM; kch = 4; kpitch = EDIM * 2;
    } else {
        A = g_encout16; B = g_Wat16; biasI = bias_ext;
        Mlim = SLEN * BATCH; ldc = HDIM; kch = 8; kpitch = HDIM * 2;
    }

    extern __shared__ char smc[];
    const uint32_t sbase = smem_u32(smc);
    const int tid = threadIdx.x;
    const int wid = tid >> 5, lane = tid & 31;
    const int m0 = blockIdx.x * 128;
    const int n0 = blockIdx.y * 128;
    const int wm = wid >> 2, wn = wid & 3;

    const char* Ag = (const char*)A + (size_t)m0 * kpitch;
    const char* Bg = (const char*)B + (size_t)n0 * kpitch;

    float acc[4][4][4];
#pragma unroll
    for (int i = 0; i < 4; i++)
#pragma unroll
        for (int j = 0; j < 4; j++)
#pragma unroll
            for (int r = 0; r < 4; r++) acc[i][j][r] = 0.0f;

    auto load_chunk = [&](int kc, int slot) {
        uint32_t st = sbase + (uint32_t)slot * 32768;
#pragma unroll
        for (int i = 0; i < 8; i++) {
            int idx = tid + (i << 8);
            int isB = idx >> 10;
            int r = (idx & 1023) >> 3;
            int seg = idx & 7;
            uint32_t dst = st + (isB ? 16384u : 0u) + (uint32_t)(r << 7)
                         + (uint32_t)(((seg ^ (r & 7)) << 4));
            const char* src = (isB ? Bg : Ag) + (size_t)r * kpitch + (size_t)kc * 128 + (seg << 4);
            cpa16(dst, src);
        }
        cpa_commit();
    };

    const int g = lane >> 3, lr = lane & 7;
    auto compute = [&](int slot) {
        uint32_t Abase = sbase + (uint32_t)slot * 32768;
        uint32_t Bbase = Abase + 16384u;
#pragma unroll
        for (int ks = 0; ks < 4; ks++) {
            uint32_t afr[4][4];
#pragma unroll
            for (int mt = 0; mt < 4; mt++) {
                int row = wm * 64 + mt * 16 + (g & 1) * 8 + lr;
                int kseg = ks * 2 + (g >> 1);
                uint32_t addr = Abase + (uint32_t)(row << 7) + (uint32_t)(((kseg ^ (row & 7)) << 4));
                LDMX4(afr[mt], addr);
            }
            uint32_t bfr[2][4];
#pragma unroll
            for (int np = 0; np < 2; np++) {
                int row = wn * 32 + np * 16 + (g >> 1) * 8 + lr;
                int kseg = ks * 2 + (g & 1);
                uint32_t addr = Bbase + (uint32_t)(row << 7) + (uint32_t)(((kseg ^ (row & 7)) << 4));
                LDMX4(bfr[np], addr);
            }
#pragma unroll
            for (int mt = 0; mt < 4; mt++)
#pragma unroll
                for (int nt = 0; nt < 4; nt++) {
                    const uint32_t* bp = &bfr[nt >> 1][(nt & 1) * 2];
                    mma16816(acc[mt][nt], afr[mt], bp[0], bp[1]);
                }
        }
    };

    load_chunk(0, 0);
    load_chunk(1, 1);
    for (int i = 0; i < kch; i++) {
        if (i + 1 < kch) cpa_wait<1>(); else cpa_wait<0>();
        __syncthreads();
        if (i + 2 < kch) load_chunk(i + 2, (i + 2) % 3);
        compute(i % 3);
    }

    const int quad = lane >> 2, tq = lane & 3;
#pragma unroll
    for (int mt = 0; mt < 4; mt++) {
        int mr0 = m0 + wm * 64 + mt * 16 + quad;
#pragma unroll
        for (int half = 0; half < 2; half++) {
            int m = mr0 + half * 8;
            if (m >= Mlim) continue;
#pragma unroll
            for (int nt = 0; nt < 4; nt++) {
                int n = n0 + wn * 32 + nt * 8 + tq * 2;
                float v0 = acc[mt][nt][half * 2 + 0] + biasI[n];
                float v1 = acc[mt][nt][half * 2 + 1] + biasI[n + 1];
                if (sel == 2) {
                    __half* crow = g_encWe16 + (size_t)m * HDIM;
                    crow[n] = __float2half(v0);
                    crow[n + 1] = __float2half(v1);
                } else {
                    float* crow = C + (size_t)m * ldc;
                    crow[n] = v0;
                    crow[n + 1] = v1;
                }
            }
        }
    }
}

// ---------------- fused encoder step: fp16 gates GEMM (64x32xK512) + LSTM ----------------
__global__ void __launch_bounds__(256, 1) enc_step16(int t) {
    extern __shared__ char sm[];
    const uint32_t Ab = smem_u32(sm);
    const uint32_t Bb = Ab + 65536;
    float* gsm = (float*)(sm + 65536 + 32768);   // [64][33]
    const int tid = threadIdx.x, bid = blockIdx.x;
    const int wid = tid >> 5, lane = tid & 31;
    const int wm = wid >> 1, wn = wid & 1;

    load_AB16<8>(Ab, Bb, g_eh16[t & 1], HDIM * 2, g_We16, HDIM * 2, bid * 32, tid);

    float acc[2][4] = {{0.f, 0.f, 0.f, 0.f}, {0.f, 0.f, 0.f, 0.f}};
    mma_64x32<8>(Ab, Bb, lane, wm, wn, acc);

    const int quad = lane >> 2, tq = lane & 3;
#pragma unroll
    for (int nt = 0; nt < 2; nt++) {
        int cb = wn * 16 + nt * 8 + tq * 2;
        int r0 = wm * 16 + quad;
        gsm[r0 * 33 + cb] = acc[nt][0];
        gsm[r0 * 33 + cb + 1] = acc[nt][1];
        gsm[(r0 + 8) * 33 + cb] = acc[nt][2];
        gsm[(r0 + 8) * 33 + cb + 1] = acc[nt][3];
    }
    __syncthreads();

    const int b = tid & 63, jl = tid >> 6;
#pragma unroll
    for (int q = 0; q < 2; q++) {
        int j2 = jl + q * 4;
        int jd = bid * 8 + j2;
        float4 gv = *reinterpret_cast<const float4*>(
            &g_xprojE[((size_t)t * 64 + b) * GDIM + (size_t)jd * 4]);
        float gi = gsm[b * 33 + j2 * 4 + 0] + gv.x;
        float gf = gsm[b * 33 + j2 * 4 + 1] + gv.y;
        float gg = gsm[b * 33 + j2 * 4 + 2] + gv.z;
        float go = gsm[b * 33 + j2 * 4 + 3] + gv.w;
        int ci = b * 512 + jd;
        float cc = sigf(gf) * g_c[ci] + sigf(gi) * tanhf(gg);
        float hh = sigf(go) * tanhf(cc);
        g_c[ci] = cc;
        __half h16 = __float2half(hh);
        g_eh16[(t + 1) & 1][ci] = h16;
        g_encout16[((size_t)b * SLEN + t) * 512 + jd] = h16;
    }
}

// ---------------- decoder hWh: fp16 GEMM (64x32xK512), direct fp32 store ----------------
__global__ void __launch_bounds__(256, 1) dec_hwh16(int t) {
    extern __shared__ char sm[];
    const uint32_t Ab = smem_u32(sm);
    const uint32_t Bb = Ab + 65536;
    const int tid = threadIdx.x, bid = blockIdx.x;
    const int wid = tid >> 5, lane = tid & 31;
    const int wm = wid >> 1, wn = wid & 1;

    load_AB16<8>(Ab, Bb, g_xh16[t & 1], 1024 * 2, g_Wh16, HDIM * 2, bid * 32, tid);

    float acc[2][4] = {{0.f, 0.f, 0.f, 0.f}, {0.f, 0.f, 0.f, 0.f}};
    mma_64x32<8>(Ab, Bb, lane, wm, wn, acc);

    const int quad = lane >> 2, tq = lane & 3;
#pragma unroll
    for (int nt = 0; nt < 2; nt++) {
        int n = bid * 32 + wn * 16 + nt * 8 + tq * 2;
        int r0 = wm * 16 + quad;
        g_hwh[r0 * 512 + n] = acc[nt][0];
        g_hwh[r0 * 512 + n + 1] = acc[nt][1];
        g_hwh[(r0 + 8) * 512 + n] = acc[nt][2];
        g_hwh[(r0 + 8) * 512 + n + 1] = acc[nt][3];
    }
}

// ---------------- decoder attention (fp16 encWe / encout inputs, half2-coalesced) ----------------
__global__ void __launch_bounds__(256, 1) k_attn(const float* __restrict__ vw, int t) {
    __shared__ float hwhs[512];
    __shared__ float vws[512];
    __shared__ float sc[128];
    __shared__ float red[128];
    const int bb = blockIdx.x;
    const int tid = threadIdx.x;
    const int cur = t & 1;

    for (int i = tid; i < 512; i += 256) {
        hwhs[i] = g_hwh[bb * 512 + i];
        vws[i] = vw[i];
    }
    __syncthreads();
    int warp = tid >> 5, lane = tid & 31;
    for (int s = warp; s < SLEN; s += 8) {
        const __half2* we2 = reinterpret_cast<const __half2*>(
            &g_encWe16[((size_t)bb * SLEN + s) * 512]);
        float a = 0.0f;
        for (int j2 = lane; j2 < 256; j2 += 32) {
            float2 wf = __half22float2(we2[j2]);
            int j = j2 * 2;
            a += tanhf(hwhs[j] + wf.x) * vws[j];
            a += tanhf(hwhs[j + 1] + wf.y) * vws[j + 1];
        }
#pragma unroll
        for (int o = 16; o > 0; o >>= 1) a += __shfl_xor_sync(0xffffffffu, a, o);
        if (lane == 0) sc[s] = a;
    }
    __syncthreads();
    if (tid < SLEN) red[tid] = sc[tid];
    __syncthreads();
    for (int o = 64; o > 0; o >>= 1) {
        if (tid < o) red[tid] = fmaxf(red[tid], red[tid + o]);
        __syncthreads();
    }
    float mx = red[0];
    __syncthreads();
    float e = 0.0f;
    if (tid < SLEN) { e = expf(sc[tid] - mx); red[tid] = e; }
    __syncthreads();
    for (int o = 64; o > 0; o >>= 1) {
        if (tid < o) red[tid] += red[tid + o];
        __syncthreads();
    }
    float inv = 1.0f / red[0];
    __syncthreads();
    if (tid < SLEN) sc[tid] = e * inv;
    __syncthreads();

    // context: thread handles columns 2*tid, 2*tid+1 (fully coalesced half2 loads)
    float c0 = 0.0f, c1 = 0.0f;
    const __half2* eo2 = reinterpret_cast<const __half2*>(
        &g_encout16[(size_t)bb * SLEN * 512]);
    for (int s = 0; s < SLEN; s++) {
        float w = sc[s];
        float2 ef = __half22float2(eo2[s * 256 + tid]);
        c0 += w * ef.x;
        c1 += w * ef.y;
    }
    __half2 hpair = __floats2half2_rn(c0, c1);
    *reinterpret_cast<__half2*>(&g_xh16[cur][bb * 1024 + 512 + tid * 2]) = hpair;
    size_t ma = ((size_t)t * 64 + bb) * 1024;
    *reinterpret_cast<__half2*>(&g_Ahf[ma + 512 + tid * 2]) = hpair;
}

// ---------------- fused decoder gates: fp16 GEMM (64x32xK1024) + LSTM ----------------
__global__ void __launch_bounds__(256, 1) dec_gates16(int t) {
    extern __shared__ char sm[];
    const uint32_t Ab = smem_u32(sm);
    const uint32_t Bb = Ab + 131072;
    float* gsm = (float*)(sm + 131072 + 65536);   // [64][33]
    const int tid = threadIdx.x, bid = blockIdx.x;
    const int wid = tid >> 5, lane = tid & 31;
    const int wm = wid >> 1, wn = wid & 1;

    load_AB16<16>(Ab, Bb, g_xh16[t & 1], 1024 * 2, g_Wd16, 1024 * 2, bid * 32, tid);

    float acc[2][4] = {{0.f, 0.f, 0.f, 0.f}, {0.f, 0.f, 0.f, 0.f}};
    mma_64x32<16>(Ab, Bb, lane, wm, wn, acc);

    const int quad = lane >> 2, tq = lane & 3;
#pragma unroll
    for (int nt = 0; nt < 2; nt++) {
        int cb = wn * 16 + nt * 8 + tq * 2;
        int r0 = wm * 16 + quad;
        gsm[r0 * 33 + cb] = acc[nt][0];
        gsm[r0 * 33 + cb + 1] = acc[nt][1];
        gsm[(r0 + 8) * 33 + cb] = acc[nt][2];
        gsm[(r0 + 8) * 33 + cb + 1] = acc[nt][3];
    }
    __syncthreads();

    const int b = tid & 63, jl = tid >> 6;
#pragma unroll
    for (int q = 0; q < 2; q++) {
        int j2 = jl + q * 4;
        int jd = bid * 8 + j2;
        float4 gv = *reinterpret_cast<const float4*>(
            &g_decxp[((size_t)t * 64 + b) * GDIM + (size_t)jd * 4]);
        float gi = gsm[b * 33 + j2 * 4 + 0] + gv.x;
        float gf = gsm[b * 33 + j2 * 4 + 1] + gv.y;
        float gg = gsm[b * 33 + j2 * 4 + 2] + gv.z;
        float go = gsm[b * 33 + j2 * 4 + 3] + gv.w;
        int ci = b * 512 + jd;
        float cc = sigf(gf) * g_c[ci] + sigf(gi) * tanhf(gg);
        float hh = sigf(go) * tanhf(cc);
        g_c[ci] = cc;
        __half h16 = __float2half(hh);
        g_xh16[(t + 1) & 1][b * 1024 + jd] = h16;
        g_Ahf[((size_t)t * 64 + b) * 1024 + jd] = h16;
    }
}

// ---------------- fp16 tensor-core fc GEMM: tile 128M x 256N, K=1024 ----------------
__global__ void __launch_bounds__(256, 1) hgemm_fc(const float* __restrict__ fc_b,
                                                   float* __restrict__ out) {
    extern __shared__ char smc[];
    const uint32_t sbase = smem_u32(smc);
    const int tid = threadIdx.x;
    const int wid = tid >> 5, lane = tid & 31;
    const int m0 = blockIdx.x * 128;
    const int n0 = blockIdx.y * 256;
    const int wm = wid >> 2;
    const int wn = wid & 3;

    const char* Ag = (const char*)g_Ahf + (size_t)m0 * (KD * 2);
    const char* Bg = (const char*)g_Bhf + (size_t)n0 * (KD * 2);

    float acc[4][8][4];
#pragma unroll
    for (int i = 0; i < 4; i++)
#pragma unroll
        for (int j = 0; j < 8; j++)
#pragma unroll
            for (int r = 0; r < 4; r++) acc[i][j][r] = 0.0f;

    auto load_chunk = [&](int kc, int slot) {
        uint32_t st = sbase + (uint32_t)slot * STGB;
#pragma unroll
        for (int i = 0; i < 12; i++) {
            int idx = tid + (i << 8);
            int isB = idx >= 1024;
            int r = (isB ? (idx - 1024) : idx) >> 3;
            int seg = idx & 7;
            uint32_t dst = st + (isB ? 16384u : 0u) + (uint32_t)(r << 7)
                         + (uint32_t)(((seg ^ (r & 7)) << 4));
            const char* src = (isB ? Bg : Ag) + (size_t)r * (KD * 2) + (size_t)kc * 128 + (seg << 4);
            cpa16(dst, src);
        }
        cpa_commit();
    };

    const int g = lane >> 3, lr = lane & 7;

    auto compute = [&](int slot) {
        uint32_t Abase = sbase + (uint32_t)slot * STGB;
        uint32_t Bbase = Abase + 16384u;
#pragma unroll
        for (int ks = 0; ks < 4; ks++) {
            uint32_t afr[4][4];
#pragma unroll
            for (int mt = 0; mt < 4; mt++) {
                int row = wm * 64 + mt * 16 + (g & 1) * 8 + lr;
                int kseg = ks * 2 + (g >> 1);
                uint32_t addr = Abase + (uint32_t)(row << 7) + (uint32_t)(((kseg ^ (row & 7)) << 4));
                LDMX4(afr[mt], addr);
            }
            uint32_t bfr[4][4];
#pragma unroll
            for (int np = 0; np < 4; np++) {
                int row = wn * 64 + np * 16 + (g >> 1) * 8 + lr;
                int kseg = ks * 2 + (g & 1);
                uint32_t addr = Bbase + (uint32_t)(row << 7) + (uint32_t)(((kseg ^ (row & 7)) << 4));
                LDMX4(bfr[np], addr);
            }
#pragma unroll
            for (int mt = 0; mt < 4; mt++)
#pragma unroll
                for (int nt = 0; nt < 8; nt++) {
                    const uint32_t* bp = &bfr[nt >> 1][(nt & 1) * 2];
                    mma16816(acc[mt][nt], afr[mt], bp[0], bp[1]);
                }
        }
    };

    load_chunk(0, 0);
    load_chunk(1, 1);
    for (int i = 0; i < NCHK; i++) {
        if (i + 1 < NCHK) cpa_wait<1>(); else cpa_wait<0>();
        __syncthreads();
        if (i + 2 < NCHK) load_chunk(i + 2, (i + 2) % 3);
        compute(i % 3);
    }

    const int quad = lane >> 2, tq = lane & 3;
#pragma unroll
    for (int mt = 0; mt < 4; mt++) {
        int mr0 = m0 + wm * 64 + mt * 16 + quad;
#pragma unroll
        for (int half = 0; half < 2; half++) {
            int m = mr0 + half * 8;
            if (m >= TD * BATCH) continue;
            int bb = m & 63, tt = m >> 6;
            float* orow = out + ((size_t)bb * TLEN + (tt + 1)) * VCAB;
#pragma unroll
            for (int nt = 0; nt < 8; nt++) {
                int n = n0 + wn * 64 + nt * 8 + tq * 2;
                float v0 = acc[mt][nt][half * 2 + 0];
                float v1 = acc[mt][nt][half * 2 + 1];
                if (n < VCAB)     orow[n]     = v0 + fc_b[n];
                if (n + 1 < VCAB) orow[n + 1] = v1 + fc_b[n + 1];
            }
        }
    }
}

// ---------------- host driver ----------------
extern "C" void kernel_launch(void* const* d_in, const int* in_sizes, int n_in,
                              void* d_out, int out_size) {
    const int*   src     = (const int*)  d_in[0];
    const int*   trg     = (const int*)  d_in[1];
    const float* enc_emb = (const float*)d_in[2];
    const float* enc_Wih = (const float*)d_in[3];
    const float* enc_Whh = (const float*)d_in[4];
    const float* enc_bih = (const float*)d_in[5];
    const float* enc_bhh = (const float*)d_in[6];
    const float* dec_emb = (const float*)d_in[7];
    const float* dec_Wih = (const float*)d_in[8];
    const float* dec_Whh = (const float*)d_in[9];
    const float* dec_bih = (const float*)d_in[10];
    const float* dec_bhh = (const float*)d_in[11];
    const float* attn_W  = (const float*)d_in[12];
    const float* attn_b  = (const float*)d_in[13];
    const float* v_w     = (const float*)d_in[14];
    const float* fc_W    = (const float*)d_in[15];
    const float* fc_b    = (const float*)d_in[16];
    float* out = (float*)d_out;
    (void)in_sizes; (void)n_in; (void)out_size;

    const int ENC_SMEM = 65536 + 32768 + 64 * 33 * 4;        // 106752
    const int HWH_SMEM = 65536 + 32768;                      // 98304
    const int DEC_SMEM = 131072 + 65536 + 64 * 33 * 4;       // 205056
    const int PROJ_SMEM = 3 * 32768;                         // 98304
    cudaFuncSetAttribute(hgemm_fc, cudaFuncAttributeMaxDynamicSharedMemorySize, 3 * STGB);
    cudaFuncSetAttribute(hgemm_proj, cudaFuncAttributeMaxDynamicSharedMemorySize, PROJ_SMEM);
    cudaFuncSetAttribute(enc_step16, cudaFuncAttributeMaxDynamicSharedMemorySize, ENC_SMEM);
    cudaFuncSetAttribute(dec_hwh16, cudaFuncAttributeMaxDynamicSharedMemorySize, HWH_SMEM);
    cudaFuncSetAttribute(dec_gates16, cudaFuncAttributeMaxDynamicSharedMemorySize, DEC_SMEM);

    // side stream (fork-join; capture-legal, proven in R13)
    int prLo = 0, prHi = 0;
    cudaDeviceGetStreamPriorityRange(&prLo, &prHi);
    cudaStream_t s2;
    cudaStreamCreateWithPriority(&s2, cudaStreamNonBlocking, prLo);
    cudaEvent_t evRoot, evDone;
    cudaEventCreateWithFlags(&evRoot, cudaEventDisableTiming);
    cudaEventCreateWithFlags(&evDone, cudaEventDisableTiming);

    // ---- main-stream setup needed by encoder path ----
    k_biasI<<<8, 256>>>(enc_bih, enc_bhh, dec_bih, dec_bhh);
    k_w16_wih<<<(int)(((size_t)GDIM * EDIM + 255) / 256), 256>>>(enc_Wih, dec_Wih);
    k_w16_enc<<<(int)(((size_t)GDIM * HDIM + 255) / 256), 256>>>(enc_Whh);
    k_gather_enc<<<SLEN * BATCH, EDIM>>>(enc_emb, src);
    k_gather_dec<<<TD * BATCH, EDIM>>>(dec_emb, trg);
    k_zero_state<<<(BATCH * HDIM + 255) / 256, 256>>>();

    // fork: side stream runs decoder-prep work concurrent with the encoder phase
    cudaEventRecord(evRoot, 0);
    cudaStreamWaitEvent(s2, evRoot, 0);
    k_w16_dec<<<(int)(((size_t)GDIM * 1024 + 255) / 256), 256, 0, s2>>>(dec_Wih, dec_Whh);
    k_w16_attn<<<(int)(((size_t)HDIM * HDIM + 255) / 256), 256, 0, s2>>>(attn_W);
    k_zero_out<<<(int)(((size_t)BATCH * VCAB + 255) / 256), 256, 0, s2>>>(out);
    k_convB_h<<<(int)(((size_t)VCAB * KD / 4 + 255) / 256), 256, 0, s2>>>(fc_W);
    hgemm_proj<<<dim3(MPAD / 128, GDIM / 128), 256, PROJ_SMEM, s2>>>(1, nullptr);
    cudaEventRecord(evDone, s2);

    // main: encoder input projection + encoder recurrence
    hgemm_proj<<<dim3((SLEN * BATCH) / 128, GDIM / 128), 256, PROJ_SMEM>>>(0, nullptr);
    for (int t = 0; t < SLEN; t++)
        enc_step16<<<64, 256, ENC_SMEM>>>(t);

    // join: side work (incl. g_Wat16) must be done before encWe projection / decoder
    cudaStreamWaitEvent((cudaStream_t)0, evDone, 0);

    // encWe = enc_out @ attn_W[:, H:]^T + attn_b (fp16 mma, fp16 output)
    hgemm_proj<<<dim3((SLEN * BATCH) / 128, HDIM / 128), 256, PROJ_SMEM>>>(2, attn_b);

    k_init_dec<<<128, 256>>>();

    // decoder: THREE kernels per step (proven R12 structure)
    for (int t = 0; t < TD; t++) {
        dec_hwh16<<<16, 256, HWH_SMEM>>>(t);
        k_attn<<<64, 256>>>(v_w, t);
        dec_gates16<<<64, 256, DEC_SMEM>>>(t);
    }

    // tensor-core fc GEMM (128 x 256 tiles)
    hgemm_fc<<<dim3(MPAD / 128, NPAD / 256), 256, 3 * STGB>>>(fc_b, out);
}